// round 1
// baseline (speedup 1.0000x reference)
#include <cuda_runtime.h>
#include <cuda_bf16.h>

// EdgeUpdate fused kernel (fp32 baseline, round 0)
//   in[e] = concat(node_inv[src[e]], node_inv[dst[e]], edge_features[e])  (256)
//   h = relu(in @ W1 + b1)          W1: [256,128]
//   u = h @ W2 + b2                 W2: [128,128]
//   out[e] = edge_features[e] + LayerNorm(u)*gamma + beta
//
// Block: 256 threads, TILE_E=64 edges. Thread grid 16(col-groups of 8) x 16(edge-groups of 4).
// Shared: in_s [64][260], h_s [64][132], b_s [32][128] = ~114 KB dynamic.

#define TILE_E   64
#define THREADS  256
#define INDIM    256
#define HDIM     128
#define IN_STRIDE 260
#define H_STRIDE  132
#define KCHUNK    32
#define LN_EPS   1e-5f

__global__ __launch_bounds__(THREADS, 1)
void edge_update_kernel(const float* __restrict__ node_inv,
                        const float* __restrict__ edge_features,
                        const void*  __restrict__ edge_src,
                        const void*  __restrict__ edge_dst,
                        const float* __restrict__ W1,
                        const float* __restrict__ b1,
                        const float* __restrict__ W2,
                        const float* __restrict__ b2,
                        const float* __restrict__ gamma,
                        const float* __restrict__ beta,
                        float* __restrict__ out,
                        int n_edges)
{
    extern __shared__ float smem[];
    float* in_s = smem;                               // 64*260
    float* h_s  = in_s + TILE_E * IN_STRIDE;          // 64*132
    float* b_s  = h_s  + TILE_E * H_STRIDE;           // 32*128 (flat, matches W row-major chunk)

    const int tid    = threadIdx.x;
    const int e_base = blockIdx.x * TILE_E;

    // ---- index dtype sniff: int64 buffers have all-zero high words ----
    const int* s32 = (const int*)edge_src;
    const bool idx64 = ((s32[1] | s32[3] | s32[5] | s32[7]) == 0);

    // ---- gather: build in_s[e][0:256] as float4 copies ----
    // 64 edges * 64 float4 = 4096 float4 ops; 16 per thread.
    #pragma unroll
    for (int it = 0; it < (TILE_E * 64) / THREADS; ++it) {
        int idx = tid + it * THREADS;
        int e   = idx >> 6;         // edge within tile
        int j   = idx & 63;         // float4 slot within the 256-float row
        int eg  = e_base + e;
        float4 v = make_float4(0.f, 0.f, 0.f, 0.f);
        if (eg < n_edges) {
            if (j < 32) {
                long long node;
                if (j < 16)
                    node = idx64 ? ((const long long*)edge_src)[eg]
                                 : (long long)((const int*)edge_src)[eg];
                else
                    node = idx64 ? ((const long long*)edge_dst)[eg]
                                 : (long long)((const int*)edge_dst)[eg];
                v = ((const float4*)node_inv)[node * 16 + (j & 15)];
            } else {
                v = ((const float4*)edge_features)[(long long)eg * 32 + (j - 32)];
            }
        }
        *(float4*)&in_s[e * IN_STRIDE + j * 4] = v;
    }
    __syncthreads();

    const int tx = tid & 15;        // column group
    const int ty = tid >> 4;        // edge group
    const int c0 = tx * 8;
    const int e0 = ty * 4;

    float acc[4][8];

    // ================= GEMM1: h = relu(in @ W1 + b1) =================
    {
        float bb[8];
        #pragma unroll
        for (int c = 0; c < 8; ++c) bb[c] = b1[c0 + c];
        #pragma unroll
        for (int i = 0; i < 4; ++i)
            #pragma unroll
            for (int c = 0; c < 8; ++c) acc[i][c] = bb[c];
    }

    for (int kb = 0; kb < INDIM; kb += KCHUNK) {
        // stage W1 chunk [kb..kb+32) x [0..128) into b_s (layout identical, flat copy)
        const float4* wsrc = (const float4*)(W1 + kb * HDIM);
        #pragma unroll
        for (int it = 0; it < (KCHUNK * HDIM / 4) / THREADS; ++it)
            ((float4*)b_s)[tid + it * THREADS] = wsrc[tid + it * THREADS];
        __syncthreads();

        #pragma unroll
        for (int k = 0; k < KCHUNK; ++k) {
            float a0 = in_s[(e0 + 0) * IN_STRIDE + kb + k];
            float a1 = in_s[(e0 + 1) * IN_STRIDE + kb + k];
            float a2 = in_s[(e0 + 2) * IN_STRIDE + kb + k];
            float a3 = in_s[(e0 + 3) * IN_STRIDE + kb + k];
            float4 bl = *(const float4*)&b_s[k * HDIM + c0];
            float4 bh = *(const float4*)&b_s[k * HDIM + c0 + 4];
            float bv[8] = {bl.x, bl.y, bl.z, bl.w, bh.x, bh.y, bh.z, bh.w};
            #pragma unroll
            for (int c = 0; c < 8; ++c) {
                acc[0][c] = fmaf(a0, bv[c], acc[0][c]);
                acc[1][c] = fmaf(a1, bv[c], acc[1][c]);
                acc[2][c] = fmaf(a2, bv[c], acc[2][c]);
                acc[3][c] = fmaf(a3, bv[c], acc[3][c]);
            }
        }
        __syncthreads();
    }

    // relu -> h_s
    #pragma unroll
    for (int i = 0; i < 4; ++i) {
        *(float4*)&h_s[(e0 + i) * H_STRIDE + c0] =
            make_float4(fmaxf(acc[i][0], 0.f), fmaxf(acc[i][1], 0.f),
                        fmaxf(acc[i][2], 0.f), fmaxf(acc[i][3], 0.f));
        *(float4*)&h_s[(e0 + i) * H_STRIDE + c0 + 4] =
            make_float4(fmaxf(acc[i][4], 0.f), fmaxf(acc[i][5], 0.f),
                        fmaxf(acc[i][6], 0.f), fmaxf(acc[i][7], 0.f));
    }

    // ================= GEMM2: u = h @ W2 + b2 =================
    {
        float bb[8];
        #pragma unroll
        for (int c = 0; c < 8; ++c) bb[c] = b2[c0 + c];
        #pragma unroll
        for (int i = 0; i < 4; ++i)
            #pragma unroll
            for (int c = 0; c < 8; ++c) acc[i][c] = bb[c];
    }

    for (int kb = 0; kb < HDIM; kb += KCHUNK) {
        const float4* wsrc = (const float4*)(W2 + kb * HDIM);
        #pragma unroll
        for (int it = 0; it < (KCHUNK * HDIM / 4) / THREADS; ++it)
            ((float4*)b_s)[tid + it * THREADS] = wsrc[tid + it * THREADS];
        __syncthreads();   // also orders h_s writes before first h_s read

        #pragma unroll
        for (int k = 0; k < KCHUNK; ++k) {
            float a0 = h_s[(e0 + 0) * H_STRIDE + kb + k];
            float a1 = h_s[(e0 + 1) * H_STRIDE + kb + k];
            float a2 = h_s[(e0 + 2) * H_STRIDE + kb + k];
            float a3 = h_s[(e0 + 3) * H_STRIDE + kb + k];
            float4 bl = *(const float4*)&b_s[k * HDIM + c0];
            float4 bh = *(const float4*)&b_s[k * HDIM + c0 + 4];
            float bv[8] = {bl.x, bl.y, bl.z, bl.w, bh.x, bh.y, bh.z, bh.w};
            #pragma unroll
            for (int c = 0; c < 8; ++c) {
                acc[0][c] = fmaf(a0, bv[c], acc[0][c]);
                acc[1][c] = fmaf(a1, bv[c], acc[1][c]);
                acc[2][c] = fmaf(a2, bv[c], acc[2][c]);
                acc[3][c] = fmaf(a3, bv[c], acc[3][c]);
            }
        }
        __syncthreads();
    }

    // ================= LayerNorm + residual =================
    // Row e is spread over 16 lanes (tx=0..15) within one half-warp; reduce via shfl_xor.
    float gm[8], bt[8];
    #pragma unroll
    for (int c = 0; c < 8; ++c) { gm[c] = gamma[c0 + c]; bt[c] = beta[c0 + c]; }

    #pragma unroll
    for (int i = 0; i < 4; ++i) {
        float s = 0.f, ss = 0.f;
        #pragma unroll
        for (int c = 0; c < 8; ++c) { s += acc[i][c]; ss += acc[i][c] * acc[i][c]; }
        #pragma unroll
        for (int m = 1; m < 16; m <<= 1) {
            s  += __shfl_xor_sync(0xffffffffu, s,  m);
            ss += __shfl_xor_sync(0xffffffffu, ss, m);
        }
        float mu  = s * (1.f / 128.f);
        float var = ss * (1.f / 128.f) - mu * mu;
        float rs  = rsqrtf(var + LN_EPS);

        int eg = e_base + e0 + i;
        if (eg < n_edges) {
            float o[8];
            #pragma unroll
            for (int c = 0; c < 8; ++c) {
                float ef = in_s[(e0 + i) * IN_STRIDE + HDIM + c0 + c];  // edge_features slice
                o[c] = ef + (acc[i][c] - mu) * rs * gm[c] + bt[c];
            }
            float4* op = (float4*)(out + (long long)eg * HDIM + c0);
            op[0] = make_float4(o[0], o[1], o[2], o[3]);
            op[1] = make_float4(o[4], o[5], o[6], o[7]);
        }
    }
}

extern "C" void kernel_launch(void* const* d_in, const int* in_sizes, int n_in,
                              void* d_out, int out_size)
{
    const float* node_inv      = (const float*)d_in[0];
    const float* edge_features = (const float*)d_in[1];
    const void*  edge_src      = d_in[2];
    const void*  edge_dst      = d_in[3];
    const float* W1            = (const float*)d_in[4];
    const float* b1            = (const float*)d_in[5];
    const float* W2            = (const float*)d_in[6];
    const float* b2            = (const float*)d_in[7];
    const float* gamma         = (const float*)d_in[8];
    const float* beta          = (const float*)d_in[9];
    float* out = (float*)d_out;

    int n_edges = in_sizes[1] / HDIM;   // derive E from edge_features (dtype-independent)

    int smem_bytes = (TILE_E * IN_STRIDE + TILE_E * H_STRIDE + KCHUNK * HDIM) * (int)sizeof(float);
    cudaFuncSetAttribute(edge_update_kernel,
                         cudaFuncAttributeMaxDynamicSharedMemorySize, smem_bytes);

    int grid = (n_edges + TILE_E - 1) / TILE_E;
    edge_update_kernel<<<grid, THREADS, smem_bytes>>>(
        node_inv, edge_features, edge_src, edge_dst,
        W1, b1, W2, b2, gamma, beta, out, n_edges);
}

// round 3
// speedup vs baseline: 2.5634x; 2.5634x over previous
#include <cuda_runtime.h>
#include <cuda_bf16.h>
#include <cstdint>

// ============================================================================
// EdgeUpdate via mma.sync.m16n8k8 tf32 (plain sm_103-target safe).
// Per CTA: tile of 128 edges x 128 channels.
//   in[e][k] (K=256, tf32-rounded, smem stride 260)  A operand
//   W chunks (32 K-rows x 128 ch, stride 136, double buffered)  B operand
//   GEMM1 -> relu+bias -> h overwrites in_s cols 0..127 -> GEMM2
//   epilogue: +b2, LayerNorm per edge (shfl + smem partials), residual from
//   in_s ef slice (cols 128..255), coalesced float2 stores.
// ============================================================================

#define THREADS   256
#define TILE      128
#define HD        128
#define LN_EPS    1e-5f
#define S_IN      260       // in_s row stride (floats)
#define S_W       136       // wbuf row stride (floats)

// smem offsets in floats
#define F_IN      0
#define F_WBUF    (128 * S_IN)                  // 33280
#define F_PART    (F_WBUF + 2 * 32 * S_W)       // + 8704 -> 41984 (float2[128][4])
#define F_STATS   (F_PART + 128 * 4 * 2)        // + 1024 -> 43008 (float2[128])
#define F_B1      (F_STATS + 256)               // 43264
#define F_B2      (F_B1 + 128)
#define F_GM      (F_B2 + 128)
#define F_BT      (F_GM + 128)
#define SMEM_FLOATS (F_BT + 128)                // 43776 floats = 175104 B

__device__ __forceinline__ uint32_t tf32r(float x) {
    uint32_t r;
    asm("cvt.rna.tf32.f32 %0, %1;" : "=r"(r) : "f"(x));
    return r;
}
__device__ __forceinline__ float tf32rf(float x) {
    return __uint_as_float(tf32r(x));
}

__device__ __forceinline__ void mma8(float* d, const uint32_t* a, const uint32_t* b) {
    asm volatile(
        "mma.sync.aligned.m16n8k8.row.col.f32.tf32.tf32.f32 "
        "{%0,%1,%2,%3}, {%4,%5,%6,%7}, {%8,%9}, {%0,%1,%2,%3};"
        : "+f"(d[0]), "+f"(d[1]), "+f"(d[2]), "+f"(d[3])
        : "r"(a[0]), "r"(a[1]), "r"(a[2]), "r"(a[3]), "r"(b[0]), "r"(b[1]));
}

__global__ __launch_bounds__(THREADS)
void edge_update_mma(const float* __restrict__ node_inv,
                     const float* __restrict__ edge_features,
                     const void*  __restrict__ edge_src,
                     const void*  __restrict__ edge_dst,
                     const float* __restrict__ W1,
                     const float* __restrict__ b1,
                     const float* __restrict__ W2,
                     const float* __restrict__ b2,
                     const float* __restrict__ gamma,
                     const float* __restrict__ beta,
                     float* __restrict__ out,
                     int n_edges)
{
    extern __shared__ float sm[];
    float* in_s  = sm + F_IN;
    float* wbuf  = sm + F_WBUF;
    float2* part  = (float2*)(sm + F_PART);
    float2* stats = (float2*)(sm + F_STATS);

    const int tid  = threadIdx.x;
    const int wid  = tid >> 5;
    const int lane = tid & 31;
    const int g    = lane >> 2;      // group id (rows)
    const int t    = lane & 3;       // thread-in-group (cols)
    const int mrow = (wid & 1) * 64; // edge-row base for this warp
    const int ncol = (wid >> 1) * 32;// channel base for this warp
    const int wN   = wid >> 1;       // which channel-quarter (for LN partials)

    const int e_base = blockIdx.x * TILE;

    // index dtype sniff (int64 buffers have zero high words)
    const int* s32 = (const int*)edge_src;
    const bool idx64 = ((s32[1] | s32[3] | s32[5] | s32[7]) == 0);

    // small constants into smem
    for (int i = tid; i < HD; i += THREADS) {
        sm[F_B1 + i] = b1[i];
        sm[F_B2 + i] = b2[i];
        sm[F_GM + i] = gamma[i];
        sm[F_BT + i] = beta[i];
    }

    // ---- gather: in_s[e][0..255] tf32-rounded ----
    #pragma unroll
    for (int it = 0; it < (TILE * 64) / THREADS; ++it) {
        int idx = tid + it * THREADS;
        int e   = idx >> 6;
        int j   = idx & 63;          // float4 slot
        int eg  = e_base + e;
        float4 v = make_float4(0.f, 0.f, 0.f, 0.f);
        if (eg < n_edges) {
            if (j < 32) {
                const void* ip = (j < 16) ? edge_src : edge_dst;
                long long node = idx64 ? ((const long long*)ip)[eg]
                                       : (long long)((const int*)ip)[eg];
                v = ((const float4*)node_inv)[node * 16 + (j & 15)];
            } else {
                v = ((const float4*)edge_features)[(long long)eg * 32 + (j - 32)];
            }
        }
        v.x = tf32rf(v.x); v.y = tf32rf(v.y); v.z = tf32rf(v.z); v.w = tf32rf(v.w);
        *(float4*)&in_s[e * S_IN + j * 4] = v;
    }

    // ---- W chunk staging (32 K-rows x 128 ch), double buffered ----
    auto stage = [&](int chunk, int buf) {
        const float* src = (chunk < 8) ? (W1 + chunk * 32 * HD)
                                       : (W2 + (chunk - 8) * 32 * HD);
        float* dst = wbuf + buf * 32 * S_W;
        #pragma unroll
        for (int it = 0; it < 4; ++it) {
            int idx = tid + it * THREADS;       // 1024 float4
            int kr  = idx >> 5;
            int c4  = idx & 31;
            float4 v = ((const float4*)src)[idx];
            v.x = tf32rf(v.x); v.y = tf32rf(v.y); v.z = tf32rf(v.z); v.w = tf32rf(v.w);
            *(float4*)&dst[kr * S_W + c4 * 4] = v;
        }
    };

    float acc[4][4][4];   // [mb][nb][reg]
    #pragma unroll
    for (int mb = 0; mb < 4; ++mb)
        #pragma unroll
        for (int nb = 0; nb < 4; ++nb)
            #pragma unroll
            for (int r = 0; r < 4; ++r) acc[mb][nb][r] = 0.f;

    stage(0, 0);
    __syncthreads();

    for (int ch = 0; ch < 12; ++ch) {
        if (ch < 11) stage(ch + 1, (ch + 1) & 1);

        const float* wb = wbuf + (ch & 1) * 32 * S_W;
        const int kA = (ch < 8) ? ch * 32 : (ch - 8) * 32;   // A col base

        #pragma unroll
        for (int ks = 0; ks < 4; ++ks) {
            const int k0 = ks * 8;
            uint32_t a[4][4];
            #pragma unroll
            for (int mb = 0; mb < 4; ++mb) {
                const float* ap = in_s + (mrow + mb * 16 + g) * S_IN + kA + k0 + t;
                a[mb][0] = __float_as_uint(ap[0]);
                a[mb][1] = __float_as_uint(ap[8 * S_IN]);
                a[mb][2] = __float_as_uint(ap[4]);
                a[mb][3] = __float_as_uint(ap[8 * S_IN + 4]);
            }
            uint32_t b[4][2];
            #pragma unroll
            for (int nb = 0; nb < 4; ++nb) {
                const float* bp = wb + (k0 + t) * S_W + ncol + nb * 8 + g;
                b[nb][0] = __float_as_uint(bp[0]);
                b[nb][1] = __float_as_uint(bp[4 * S_W]);
            }
            #pragma unroll
            for (int mb = 0; mb < 4; ++mb)
                #pragma unroll
                for (int nb = 0; nb < 4; ++nb)
                    mma8(acc[mb][nb], a[mb], b[nb]);
        }

        if (ch == 7) {
            // h = relu(D1 + b1), tf32-rounded, into in_s cols 0..127
            #pragma unroll
            for (int mb = 0; mb < 4; ++mb) {
                const int r0 = mrow + mb * 16 + g;
                #pragma unroll
                for (int nb = 0; nb < 4; ++nb) {
                    const int c0 = ncol + nb * 8 + 2 * t;
                    const float bb0 = sm[F_B1 + c0], bb1 = sm[F_B1 + c0 + 1];
                    float2 h0, h1;
                    h0.x = __uint_as_float(tf32r(fmaxf(acc[mb][nb][0] + bb0, 0.f)));
                    h0.y = __uint_as_float(tf32r(fmaxf(acc[mb][nb][1] + bb1, 0.f)));
                    h1.x = __uint_as_float(tf32r(fmaxf(acc[mb][nb][2] + bb0, 0.f)));
                    h1.y = __uint_as_float(tf32r(fmaxf(acc[mb][nb][3] + bb1, 0.f)));
                    *(float2*)&in_s[r0 * S_IN + c0]       = h0;
                    *(float2*)&in_s[(r0 + 8) * S_IN + c0] = h1;
                }
            }
            // reset accumulators for GEMM2
            #pragma unroll
            for (int mb = 0; mb < 4; ++mb)
                #pragma unroll
                for (int nb = 0; nb < 4; ++nb)
                    #pragma unroll
                    for (int r = 0; r < 4; ++r) acc[mb][nb][r] = 0.f;
        }
        __syncthreads();
    }

    // ---- epilogue: u = D2 + b2; LayerNorm; residual; store ----
    #pragma unroll
    for (int mb = 0; mb < 4; ++mb)
        #pragma unroll
        for (int nb = 0; nb < 4; ++nb) {
            const int c0 = ncol + nb * 8 + 2 * t;
            acc[mb][nb][0] += sm[F_B2 + c0];
            acc[mb][nb][1] += sm[F_B2 + c0 + 1];
            acc[mb][nb][2] += sm[F_B2 + c0];
            acc[mb][nb][3] += sm[F_B2 + c0 + 1];
        }

    // partial sums per edge over this warp's 32 channels
    #pragma unroll
    for (int mb = 0; mb < 4; ++mb) {
        float s0 = 0.f, ss0 = 0.f, s1 = 0.f, ss1 = 0.f;
        #pragma unroll
        for (int nb = 0; nb < 4; ++nb) {
            float u0 = acc[mb][nb][0], u1 = acc[mb][nb][1];
            float u2 = acc[mb][nb][2], u3 = acc[mb][nb][3];
            s0 += u0 + u1;  ss0 += u0 * u0 + u1 * u1;
            s1 += u2 + u3;  ss1 += u2 * u2 + u3 * u3;
        }
        #pragma unroll
        for (int m = 1; m < 4; m <<= 1) {
            s0  += __shfl_xor_sync(0xffffffffu, s0,  m);
            ss0 += __shfl_xor_sync(0xffffffffu, ss0, m);
            s1  += __shfl_xor_sync(0xffffffffu, s1,  m);
            ss1 += __shfl_xor_sync(0xffffffffu, ss1, m);
        }
        if (t == 0) {
            int e0 = mrow + mb * 16 + g;
            part[e0 * 4 + wN]       = make_float2(s0, ss0);
            part[(e0 + 8) * 4 + wN] = make_float2(s1, ss1);
        }
    }
    __syncthreads();

    if (tid < TILE) {
        float s = 0.f, ss = 0.f;
        #pragma unroll
        for (int q = 0; q < 4; ++q) {
            float2 p = part[tid * 4 + q];
            s += p.x; ss += p.y;
        }
        float mu  = s * (1.f / 128.f);
        float var = ss * (1.f / 128.f) - mu * mu;
        stats[tid] = make_float2(mu, rsqrtf(var + LN_EPS));
    }
    __syncthreads();

    #pragma unroll
    for (int mb = 0; mb < 4; ++mb) {
        const int r0 = mrow + mb * 16 + g;
        const float2 st0 = stats[r0];
        const float2 st1 = stats[r0 + 8];
        const int eg0 = e_base + r0;
        const int eg1 = eg0 + 8;
        #pragma unroll
        for (int nb = 0; nb < 4; ++nb) {
            const int c0 = ncol + nb * 8 + 2 * t;
            const float gm0 = sm[F_GM + c0], gm1 = sm[F_GM + c0 + 1];
            const float bt0 = sm[F_BT + c0], bt1 = sm[F_BT + c0 + 1];
            if (eg0 < n_edges) {
                float2 ef = *(const float2*)&in_s[r0 * S_IN + HD + c0];
                float2 o;
                o.x = ef.x + (acc[mb][nb][0] - st0.x) * st0.y * gm0 + bt0;
                o.y = ef.y + (acc[mb][nb][1] - st0.x) * st0.y * gm1 + bt1;
                *(float2*)&out[(long long)eg0 * HD + c0] = o;
            }
            if (eg1 < n_edges) {
                float2 ef = *(const float2*)&in_s[(r0 + 8) * S_IN + HD + c0];
                float2 o;
                o.x = ef.x + (acc[mb][nb][2] - st1.x) * st1.y * gm0 + bt0;
                o.y = ef.y + (acc[mb][nb][3] - st1.x) * st1.y * gm1 + bt1;
                *(float2*)&out[(long long)eg1 * HD + c0] = o;
            }
        }
    }
}

extern "C" void kernel_launch(void* const* d_in, const int* in_sizes, int n_in,
                              void* d_out, int out_size)
{
    const float* node_inv      = (const float*)d_in[0];
    const float* edge_features = (const float*)d_in[1];
    const void*  edge_src      = d_in[2];
    const void*  edge_dst      = d_in[3];
    const float* W1            = (const float*)d_in[4];
    const float* b1            = (const float*)d_in[5];
    const float* W2            = (const float*)d_in[6];
    const float* b2            = (const float*)d_in[7];
    const float* gamma         = (const float*)d_in[8];
    const float* beta          = (const float*)d_in[9];
    float* out = (float*)d_out;

    int n_edges = in_sizes[1] / HD;

    int smem_bytes = SMEM_FLOATS * (int)sizeof(float);
    cudaFuncSetAttribute(edge_update_mma,
                         cudaFuncAttributeMaxDynamicSharedMemorySize, smem_bytes);

    int grid = (n_edges + TILE - 1) / TILE;
    edge_update_mma<<<grid, THREADS, smem_bytes>>>(
        node_inv, edge_features, edge_src, edge_dst,
        W1, b1, W2, b2, gamma, beta, out, n_edges);
}

// round 4
// speedup vs baseline: 3.6741x; 1.4333x over previous
#include <cuda_runtime.h>
#include <cuda_bf16.h>
#include <cstdint>

// ============================================================================
// EdgeUpdate via mma.sync.m16n8k8 tf32, round 3: latency-hiding build.
//  - 512 threads (16 warps), warp tile 32 edges x 32 channels
//  - W pre-rounded to tf32 in __device__ g_W by a prep kernel
//  - cp.async double-buffered 64-row W chunks (6 chunks total)
//  - gather -> in_s (stride 260), h overwrites in_s cols 0..127 after GEMM1
//  - epilogue: +b2, per-edge LayerNorm (shfl + smem partials), residual
// ============================================================================

#define THREADS   512
#define TILE      128
#define HD        128
#define KC        64        // K-chunk rows
#define LN_EPS    1e-5f
#define S_IN      260       // in_s row stride (floats)
#define S_W       136       // wbuf row stride (floats)

// smem float offsets
#define F_IN      0
#define F_WBUF    (128 * S_IN)                  // 33280
#define F_PART    (F_WBUF + 2 * KC * S_W)       // 50688 (float2[128][4])
#define F_STATS   (F_PART + 128 * 4 * 2)        // 51712 (float2[128])
#define F_B1      (F_STATS + 256)               // 51968
#define F_B2      (F_B1 + 128)
#define F_GM      (F_B2 + 128)
#define F_BT      (F_GM + 128)
#define SMEM_FLOATS (F_BT + 128)                // 52480 floats = 209920 B

__device__ float g_W[49152];   // tf32-rounded W1 (32768) ++ W2 (16384)

__device__ __forceinline__ uint32_t tf32r(float x) {
    uint32_t r;
    asm("cvt.rna.tf32.f32 %0, %1;" : "=r"(r) : "f"(x));
    return r;
}
__device__ __forceinline__ float tf32rf(float x) { return __uint_as_float(tf32r(x)); }

__device__ __forceinline__ void mma8(float* d, const uint32_t* a, const uint32_t* b) {
    asm volatile(
        "mma.sync.aligned.m16n8k8.row.col.f32.tf32.tf32.f32 "
        "{%0,%1,%2,%3}, {%4,%5,%6,%7}, {%8,%9}, {%0,%1,%2,%3};"
        : "+f"(d[0]), "+f"(d[1]), "+f"(d[2]), "+f"(d[3])
        : "r"(a[0]), "r"(a[1]), "r"(a[2]), "r"(a[3]), "r"(b[0]), "r"(b[1]));
}

__device__ __forceinline__ uint32_t smem_u32(const void* p) {
    uint32_t a;
    asm("{ .reg .u64 t; cvta.to.shared.u64 t, %1; cvt.u32.u64 %0, t; }" : "=r"(a) : "l"(p));
    return a;
}
__device__ __forceinline__ void cp16(uint32_t dst, const void* src) {
    asm volatile("cp.async.cg.shared.global [%0], [%1], 16;" :: "r"(dst), "l"(src));
}
#define CP_COMMIT() asm volatile("cp.async.commit_group;" ::: "memory")
#define CP_WAIT0()  asm volatile("cp.async.wait_group 0;" ::: "memory")

__global__ void prep_w(const float* __restrict__ W1, const float* __restrict__ W2) {
    int i = blockIdx.x * blockDim.x + threadIdx.x;
    if (i < 32768)      g_W[i] = tf32rf(W1[i]);
    else if (i < 49152) g_W[i] = tf32rf(W2[i - 32768]);
}

__global__ __launch_bounds__(THREADS, 1)
void edge_update_mma(const float* __restrict__ node_inv,
                     const float* __restrict__ edge_features,
                     const void*  __restrict__ edge_src,
                     const void*  __restrict__ edge_dst,
                     const float* __restrict__ b1,
                     const float* __restrict__ b2,
                     const float* __restrict__ gamma,
                     const float* __restrict__ beta,
                     float* __restrict__ out,
                     int n_edges)
{
    extern __shared__ float sm[];
    float*  in_s  = sm + F_IN;
    float*  wbuf  = sm + F_WBUF;
    float2* part  = (float2*)(sm + F_PART);
    float2* stats = (float2*)(sm + F_STATS);
    const uint32_t sb_wbuf = smem_u32(wbuf);

    const int tid  = threadIdx.x;
    const int wid  = tid >> 5;
    const int lane = tid & 31;
    const int g    = lane >> 2;        // 0..7
    const int t    = lane & 3;         // 0..3
    const int mrow = (wid >> 2) * 32;  // edge-row base (4 quarters)
    const int ncol = (wid & 3) * 32;   // channel base (4 quarters)
    const int wN   = wid & 3;          // LN partial slot

    const int e_base = blockIdx.x * TILE;

    // index dtype sniff (int64 buffers have zero high words)
    const int* s32 = (const int*)edge_src;
    const bool idx64 = ((s32[1] | s32[3] | s32[5] | s32[7]) == 0);

    // ---- stage(0) first: W chunk flight overlaps the gather ----
    auto stage = [&](int ch) {
        const float4* src = (const float4*)(g_W + (ch < 4 ? ch * KC * HD
                                                          : 32768 + (ch - 4) * KC * HD));
        uint32_t dstb = sb_wbuf + (uint32_t)(ch & 1) * (KC * S_W * 4);
        #pragma unroll
        for (int i = 0; i < (KC * HD / 4) / THREADS; ++i) {   // 4 iters
            int idx = tid + i * THREADS;
            int kr  = idx >> 5;
            int c4  = idx & 31;
            cp16(dstb + (uint32_t)(kr * S_W + c4 * 4) * 4, src + idx);
        }
        CP_COMMIT();
    };
    stage(0);

    // small constants into smem
    if (tid < 128) {
        sm[F_B1 + tid] = b1[tid];
        sm[F_B2 + tid] = b2[tid];
        sm[F_GM + tid] = gamma[tid];
        sm[F_BT + tid] = beta[tid];
    }

    // ---- gather: in_s[e][0..255] tf32-rounded ----
    #pragma unroll
    for (int it = 0; it < (TILE * 64) / THREADS; ++it) {      // 16 iters
        int idx = tid + it * THREADS;
        int e   = idx >> 6;
        int j   = idx & 63;
        int eg  = e_base + e;
        float4 v = make_float4(0.f, 0.f, 0.f, 0.f);
        if (eg < n_edges) {
            if (j < 32) {
                const void* ip = (j < 16) ? edge_src : edge_dst;
                long long node = idx64 ? ((const long long*)ip)[eg]
                                       : (long long)((const int*)ip)[eg];
                v = ((const float4*)node_inv)[node * 16 + (j & 15)];
            } else {
                v = ((const float4*)edge_features)[(long long)eg * 32 + (j - 32)];
            }
        }
        v.x = tf32rf(v.x); v.y = tf32rf(v.y); v.z = tf32rf(v.z); v.w = tf32rf(v.w);
        *(float4*)&in_s[e * S_IN + j * 4] = v;
    }

    float acc[2][4][4];
    #pragma unroll
    for (int mb = 0; mb < 2; ++mb)
        #pragma unroll
        for (int nb = 0; nb < 4; ++nb)
            #pragma unroll
            for (int r = 0; r < 4; ++r) acc[mb][nb][r] = 0.f;

    // ---- mainloop: 6 chunks of K=64 (4 for GEMM1, 2 for GEMM2) ----
    for (int ch = 0; ch < 6; ++ch) {
        CP_WAIT0();
        __syncthreads();                 // buf[ch&1] visible; prior compute done
        if (ch < 5) stage(ch + 1);       // fill other buffer, overlapped

        const float* wb = wbuf + (ch & 1) * KC * S_W;
        const int kA = (ch < 4) ? ch * KC : (ch - 4) * KC;

        #pragma unroll
        for (int ks = 0; ks < 8; ++ks) {
            const int k0 = ks * 8;
            uint32_t a[2][4];
            #pragma unroll
            for (int mb = 0; mb < 2; ++mb) {
                const float* ap = in_s + (mrow + mb * 16 + g) * S_IN + kA + k0 + t;
                a[mb][0] = __float_as_uint(ap[0]);
                a[mb][1] = __float_as_uint(ap[8 * S_IN]);
                a[mb][2] = __float_as_uint(ap[4]);
                a[mb][3] = __float_as_uint(ap[8 * S_IN + 4]);
            }
            uint32_t b[4][2];
            #pragma unroll
            for (int nb = 0; nb < 4; ++nb) {
                const float* bp = wb + (k0 + t) * S_W + ncol + nb * 8 + g;
                b[nb][0] = __float_as_uint(bp[0]);
                b[nb][1] = __float_as_uint(bp[4 * S_W]);
            }
            #pragma unroll
            for (int mb = 0; mb < 2; ++mb)
                #pragma unroll
                for (int nb = 0; nb < 4; ++nb)
                    mma8(acc[mb][nb], a[mb], b[nb]);
        }

        if (ch == 3) {
            // h = relu(D1 + b1), tf32-rounded, into in_s cols 0..127
            #pragma unroll
            for (int mb = 0; mb < 2; ++mb) {
                const int r0 = mrow + mb * 16 + g;
                #pragma unroll
                for (int nb = 0; nb < 4; ++nb) {
                    const int c0 = ncol + nb * 8 + 2 * t;
                    const float bb0 = sm[F_B1 + c0], bb1 = sm[F_B1 + c0 + 1];
                    float2 h0, h1;
                    h0.x = tf32rf(fmaxf(acc[mb][nb][0] + bb0, 0.f));
                    h0.y = tf32rf(fmaxf(acc[mb][nb][1] + bb1, 0.f));
                    h1.x = tf32rf(fmaxf(acc[mb][nb][2] + bb0, 0.f));
                    h1.y = tf32rf(fmaxf(acc[mb][nb][3] + bb1, 0.f));
                    *(float2*)&in_s[r0 * S_IN + c0]       = h0;
                    *(float2*)&in_s[(r0 + 8) * S_IN + c0] = h1;
                }
            }
            #pragma unroll
            for (int mb = 0; mb < 2; ++mb)
                #pragma unroll
                for (int nb = 0; nb < 4; ++nb)
                    #pragma unroll
                    for (int r = 0; r < 4; ++r) acc[mb][nb][r] = 0.f;
            // next-iteration top __syncthreads orders h-store vs GEMM2 reads
        }
    }

    // ---- epilogue: u = D2 + b2; LayerNorm; residual; store ----
    #pragma unroll
    for (int mb = 0; mb < 2; ++mb)
        #pragma unroll
        for (int nb = 0; nb < 4; ++nb) {
            const int c0 = ncol + nb * 8 + 2 * t;
            acc[mb][nb][0] += sm[F_B2 + c0];
            acc[mb][nb][1] += sm[F_B2 + c0 + 1];
            acc[mb][nb][2] += sm[F_B2 + c0];
            acc[mb][nb][3] += sm[F_B2 + c0 + 1];
        }

    #pragma unroll
    for (int mb = 0; mb < 2; ++mb) {
        float s0 = 0.f, ss0 = 0.f, s1 = 0.f, ss1 = 0.f;
        #pragma unroll
        for (int nb = 0; nb < 4; ++nb) {
            float u0 = acc[mb][nb][0], u1 = acc[mb][nb][1];
            float u2 = acc[mb][nb][2], u3 = acc[mb][nb][3];
            s0 += u0 + u1;  ss0 += u0 * u0 + u1 * u1;
            s1 += u2 + u3;  ss1 += u2 * u2 + u3 * u3;
        }
        #pragma unroll
        for (int m = 1; m < 4; m <<= 1) {
            s0  += __shfl_xor_sync(0xffffffffu, s0,  m);
            ss0 += __shfl_xor_sync(0xffffffffu, ss0, m);
            s1  += __shfl_xor_sync(0xffffffffu, s1,  m);
            ss1 += __shfl_xor_sync(0xffffffffu, ss1, m);
        }
        if (t == 0) {
            int e0 = mrow + mb * 16 + g;
            part[e0 * 4 + wN]       = make_float2(s0, ss0);
            part[(e0 + 8) * 4 + wN] = make_float2(s1, ss1);
        }
    }
    __syncthreads();

    if (tid < TILE) {
        float s = 0.f, ss = 0.f;
        #pragma unroll
        for (int q = 0; q < 4; ++q) {
            float2 p = part[tid * 4 + q];
            s += p.x; ss += p.y;
        }
        float mu  = s * (1.f / 128.f);
        float var = ss * (1.f / 128.f) - mu * mu;
        stats[tid] = make_float2(mu, rsqrtf(var + LN_EPS));
    }
    __syncthreads();

    #pragma unroll
    for (int mb = 0; mb < 2; ++mb) {
        const int r0 = mrow + mb * 16 + g;
        const float2 st0 = stats[r0];
        const float2 st1 = stats[r0 + 8];
        const int eg0 = e_base + r0;
        const int eg1 = eg0 + 8;
        #pragma unroll
        for (int nb = 0; nb < 4; ++nb) {
            const int c0 = ncol + nb * 8 + 2 * t;
            const float gm0 = sm[F_GM + c0], gm1 = sm[F_GM + c0 + 1];
            const float bt0 = sm[F_BT + c0], bt1 = sm[F_BT + c0 + 1];
            if (eg0 < n_edges) {
                float2 ef = *(const float2*)&in_s[r0 * S_IN + HD + c0];
                float2 o;
                o.x = ef.x + (acc[mb][nb][0] - st0.x) * st0.y * gm0 + bt0;
                o.y = ef.y + (acc[mb][nb][1] - st0.x) * st0.y * gm1 + bt1;
                *(float2*)&out[(long long)eg0 * HD + c0] = o;
            }
            if (eg1 < n_edges) {
                float2 ef = *(const float2*)&in_s[(r0 + 8) * S_IN + HD + c0];
                float2 o;
                o.x = ef.x + (acc[mb][nb][2] - st1.x) * st1.y * gm0 + bt0;
                o.y = ef.y + (acc[mb][nb][3] - st1.x) * st1.y * gm1 + bt1;
                *(float2*)&out[(long long)eg1 * HD + c0] = o;
            }
        }
    }
}

extern "C" void kernel_launch(void* const* d_in, const int* in_sizes, int n_in,
                              void* d_out, int out_size)
{
    const float* node_inv      = (const float*)d_in[0];
    const float* edge_features = (const float*)d_in[1];
    const void*  edge_src      = d_in[2];
    const void*  edge_dst      = d_in[3];
    const float* W1            = (const float*)d_in[4];
    const float* b1            = (const float*)d_in[5];
    const float* W2            = (const float*)d_in[6];
    const float* b2            = (const float*)d_in[7];
    const float* gamma         = (const float*)d_in[8];
    const float* beta          = (const float*)d_in[9];
    float* out = (float*)d_out;

    int n_edges = in_sizes[1] / HD;

    prep_w<<<(49152 + 255) / 256, 256>>>(W1, W2);

    int smem_bytes = SMEM_FLOATS * (int)sizeof(float);
    cudaFuncSetAttribute(edge_update_mma,
                         cudaFuncAttributeMaxDynamicSharedMemorySize, smem_bytes);

    int grid = (n_edges + TILE - 1) / TILE;
    edge_update_mma<<<grid, THREADS, smem_bytes>>>(
        node_inv, edge_features, edge_src, edge_dst,
        b1, b2, gamma, beta, out, n_edges);
}

// round 7
// speedup vs baseline: 5.1248x; 1.3949x over previous
#include <cuda_runtime.h>
#include <cuda_bf16.h>
#include <cstdint>

// ============================================================================
// EdgeUpdate, round 6: R4 design with the W-staging cp.async bug fixed.
//  - mma.sync m16n8k8 tf32, 512 threads, tile 128 edges x 128 ch, warp 32x32
//  - prep kernel stores W1^T / W2^T (channel-major [c][k]), tf32-rna-rounded
//  - W chunks (KC=64 k-floats per channel) cp.async double-buffered, stride 68
//  - gather: indices staged to smem, then cp.async 16B per (edge, quad)
//  - A and B fragments via ldmatrix.m8n8.x4.b16 (fp32-as-2xb16 trick)
//  - h = relu(D1+b1) rna-rounded, overwrites in_s cols 0..127
//  - epilogue: +b2, per-edge LayerNorm, residual from exact fp32 ef in smem
// ============================================================================

#define THREADS   512
#define TILE      128
#define HD        128
#define KC        64
#define LN_EPS    1e-5f
#define S_IN      260       // in_s row stride (floats)
#define S_WT      68        // transposed W chunk row stride (floats)

// smem float offsets
#define F_IN      0
#define F_WBUF    (128 * S_IN)                   // 33280
#define F_PART    (F_WBUF + 2 * 128 * S_WT)      // 50688 (float2[128][4]) / idx alias
#define F_STATS   (F_PART + 128 * 4 * 2)         // 51712 (float2[128])
#define F_B1      (F_STATS + 256)
#define F_B2      (F_B1 + 128)
#define F_GM      (F_B2 + 128)
#define F_BT      (F_GM + 128)
#define SMEM_FLOATS (F_BT + 128)                 // 52480 floats = 209920 B

__device__ float g_Wt[49152];   // W1^T [128][256] ++ W2^T [128][128], tf32-rounded

__device__ __forceinline__ uint32_t tf32r(float x) {
    uint32_t r;
    asm("cvt.rna.tf32.f32 %0, %1;" : "=r"(r) : "f"(x));
    return r;
}
__device__ __forceinline__ float tf32rf(float x) { return __uint_as_float(tf32r(x)); }

__device__ __forceinline__ void mma8(float* d, const uint32_t* a, const uint32_t* b) {
    asm volatile(
        "mma.sync.aligned.m16n8k8.row.col.f32.tf32.tf32.f32 "
        "{%0,%1,%2,%3}, {%4,%5,%6,%7}, {%8,%9}, {%0,%1,%2,%3};"
        : "+f"(d[0]), "+f"(d[1]), "+f"(d[2]), "+f"(d[3])
        : "r"(a[0]), "r"(a[1]), "r"(a[2]), "r"(a[3]), "r"(b[0]), "r"(b[1]));
}

#define LDSM4(r, addr)                                                          \
    asm volatile("ldmatrix.sync.aligned.m8n8.x4.shared.b16 {%0,%1,%2,%3}, [%4];"\
        : "=r"((r)[0]), "=r"((r)[1]), "=r"((r)[2]), "=r"((r)[3]) : "r"(addr))

__device__ __forceinline__ uint32_t smem_u32(const void* p) {
    uint32_t a;
    asm("{ .reg .u64 t; cvta.to.shared.u64 t, %1; cvt.u32.u64 %0, t; }" : "=r"(a) : "l"(p));
    return a;
}
__device__ __forceinline__ void cp16(uint32_t dst, const void* src) {
    asm volatile("cp.async.cg.shared.global [%0], [%1], 16;" :: "r"(dst), "l"(src));
}
#define CP_COMMIT() asm volatile("cp.async.commit_group;" ::: "memory")
#define CP_WAIT0()  asm volatile("cp.async.wait_group 0;" ::: "memory")

__global__ void prep_w(const float* __restrict__ W1, const float* __restrict__ W2) {
    int i = blockIdx.x * blockDim.x + threadIdx.x;      // i = c*K + k
    if (i < 32768) {
        int c = i >> 8, k = i & 255;
        g_Wt[i] = tf32rf(W1[k * HD + c]);
    } else if (i < 49152) {
        int j = i - 32768;
        int c = j >> 7, k = j & 127;
        g_Wt[i] = tf32rf(W2[k * HD + c]);
    }
}

__global__ __launch_bounds__(THREADS, 1)
void edge_update_mma(const float* __restrict__ node_inv,
                     const float* __restrict__ edge_features,
                     const void*  __restrict__ edge_src,
                     const void*  __restrict__ edge_dst,
                     const float* __restrict__ b1,
                     const float* __restrict__ b2,
                     const float* __restrict__ gamma,
                     const float* __restrict__ beta,
                     float* __restrict__ out,
                     int n_edges)
{
    extern __shared__ float sm[];
    float*  in_s  = sm + F_IN;
    float*  wbuf  = sm + F_WBUF;
    float2* part  = (float2*)(sm + F_PART);
    float2* stats = (float2*)(sm + F_STATS);
    int*    idxs  = (int*)(sm + F_PART);       // alias: used only during gather

    const uint32_t inb  = smem_u32(in_s);
    const uint32_t wbb  = smem_u32(wbuf);

    const int tid  = threadIdx.x;
    const int wid  = tid >> 5;
    const int lane = tid & 31;
    const int g    = lane >> 2;
    const int t    = lane & 3;
    const int mrow = (wid >> 2) * 32;
    const int ncol = (wid & 3) * 32;
    const int wN   = wid & 3;

    const int e_base = blockIdx.x * TILE;

    // index dtype sniff (int64 buffers have zero high words)
    const int* s32c = (const int*)edge_src;
    const bool idx64 = ((s32c[1] | s32c[3] | s32c[5] | s32c[7]) == 0);

    // ---- W chunk staging: 128 channel rows x KC floats = 2048 x 16B ----
    auto stage = [&](int ch) {
        const float* src;
        int kA, kstr;
        if (ch < 4) { src = g_Wt;         kA = ch * KC;       kstr = 256; }
        else        { src = g_Wt + 32768; kA = (ch - 4) * KC; kstr = 128; }
        uint32_t dstb = wbb + (uint32_t)((ch & 1) * 128 * S_WT) * 4u;
        #pragma unroll
        for (int i = 0; i < 4; ++i) {
            int idx = tid + i * THREADS;   // 0..2047
            int c   = idx >> 4;            // channel row 0..127
            int q   = idx & 15;            // 4-float quad 0..15
            cp16(dstb + (uint32_t)(c * S_WT + q * 4) * 4u,
                 src + c * kstr + kA + q * 4);
        }
        CP_COMMIT();
    };
    stage(0);

    // small constants
    if (tid < 128) {
        sm[F_B1 + tid] = b1[tid];
        sm[F_B2 + tid] = b2[tid];
        sm[F_GM + tid] = gamma[tid];
        sm[F_BT + tid] = beta[tid];
    }

    // ---- stage edge indices (low words work for both int32/int64) ----
    if (tid < 256) {
        int e  = tid & 127;
        int eg = e_base + e;
        if (eg >= n_edges) eg = n_edges - 1;
        const int* p = (const int*)((tid < 128) ? edge_src : edge_dst);
        idxs[tid] = idx64 ? p[2 * eg] : p[eg];
    }
    __syncthreads();

    // ---- gather via cp.async: 128 edges x 64 16B-quads ----
    {
        int eg_clamp_max = n_edges - 1;
        #pragma unroll
        for (int it = 0; it < (TILE * 64) / THREADS; ++it) {    // 16 iters
            int idx = tid + it * THREADS;
            int e   = idx >> 6;
            int j   = idx & 63;
            uint32_t dst = inb + (uint32_t)(e * S_IN + j * 4) * 4u;
            if (j < 32) {
                int node = idxs[(j < 16 ? 0 : 128) + e];
                cp16(dst, node_inv + (long long)node * 64 + (j & 15) * 4);
            } else {
                int eg = e_base + e; if (eg > eg_clamp_max) eg = eg_clamp_max;
                cp16(dst, edge_features + (long long)eg * HD + (j - 32) * 4);
            }
        }
        CP_COMMIT();
    }

    // per-lane static ldmatrix offsets (bytes)
    const uint32_t a_off = (uint32_t)((mrow + (lane & 7) + ((lane >> 3) & 1) * 8) * S_IN
                                      + ((lane >> 4) & 1) * 4) * 4u;
    const uint32_t b_off = (uint32_t)((ncol + (lane & 7) + ((lane >> 4) & 1) * 8) * S_WT
                                      + ((lane >> 3) & 1) * 4) * 4u;

    float acc[2][4][4];
    #pragma unroll
    for (int mb = 0; mb < 2; ++mb)
        #pragma unroll
        for (int nb = 0; nb < 4; ++nb)
            #pragma unroll
            for (int r = 0; r < 4; ++r) acc[mb][nb][r] = 0.f;

    // ---- mainloop: 6 chunks of K=64 (4 GEMM1, 2 GEMM2) ----
    for (int ch = 0; ch < 6; ++ch) {
        CP_WAIT0();
        __syncthreads();
        if (ch < 5) stage(ch + 1);

        const uint32_t wchunk = wbb + (uint32_t)((ch & 1) * 128 * S_WT) * 4u;
        const int kA = (ch < 4) ? ch * KC : (ch - 4) * KC;
        const uint32_t abase = inb + a_off + (uint32_t)kA * 4u;
        const uint32_t bbase = wchunk + b_off;

        #pragma unroll
        for (int ks = 0; ks < 8; ++ks) {
            const uint32_t k0b = (uint32_t)(ks * 8) * 4u;
            uint32_t a[2][4], b[2][4];
            LDSM4(a[0], abase + k0b);
            LDSM4(a[1], abase + (uint32_t)(16 * S_IN) * 4u + k0b);
            LDSM4(b[0], bbase + k0b);
            LDSM4(b[1], bbase + (uint32_t)(16 * S_WT) * 4u + k0b);
            #pragma unroll
            for (int mb = 0; mb < 2; ++mb) {
                mma8(acc[mb][0], a[mb], b[0]);
                mma8(acc[mb][1], a[mb], b[0] + 2);
                mma8(acc[mb][2], a[mb], b[1]);
                mma8(acc[mb][3], a[mb], b[1] + 2);
            }
        }

        if (ch == 3) {
            // h = relu(D1 + b1), rna tf32, into in_s cols 0..127
            #pragma unroll
            for (int mb = 0; mb < 2; ++mb) {
                const int r0 = mrow + mb * 16 + g;
                #pragma unroll
                for (int nb = 0; nb < 4; ++nb) {
                    const int c0 = ncol + nb * 8 + 2 * t;
                    const float bb0 = sm[F_B1 + c0], bb1 = sm[F_B1 + c0 + 1];
                    float2 h0, h1;
                    h0.x = tf32rf(fmaxf(acc[mb][nb][0] + bb0, 0.f));
                    h0.y = tf32rf(fmaxf(acc[mb][nb][1] + bb1, 0.f));
                    h1.x = tf32rf(fmaxf(acc[mb][nb][2] + bb0, 0.f));
                    h1.y = tf32rf(fmaxf(acc[mb][nb][3] + bb1, 0.f));
                    *(float2*)&in_s[r0 * S_IN + c0]       = h0;
                    *(float2*)&in_s[(r0 + 8) * S_IN + c0] = h1;
                }
            }
            #pragma unroll
            for (int mb = 0; mb < 2; ++mb)
                #pragma unroll
                for (int nb = 0; nb < 4; ++nb)
                    #pragma unroll
                    for (int r = 0; r < 4; ++r) acc[mb][nb][r] = 0.f;
            // next-iteration top __syncthreads orders h-store vs GEMM2 reads
        }
    }

    // ---- epilogue: u = D2 + b2; LayerNorm; residual; store ----
    #pragma unroll
    for (int mb = 0; mb < 2; ++mb)
        #pragma unroll
        for (int nb = 0; nb < 4; ++nb) {
            const int c0 = ncol + nb * 8 + 2 * t;
            acc[mb][nb][0] += sm[F_B2 + c0];
            acc[mb][nb][1] += sm[F_B2 + c0 + 1];
            acc[mb][nb][2] += sm[F_B2 + c0];
            acc[mb][nb][3] += sm[F_B2 + c0 + 1];
        }

    __syncthreads();   // idxs alias dead; part now safe to write

    #pragma unroll
    for (int mb = 0; mb < 2; ++mb) {
        float s0 = 0.f, ss0 = 0.f, s1 = 0.f, ss1 = 0.f;
        #pragma unroll
        for (int nb = 0; nb < 4; ++nb) {
            float u0 = acc[mb][nb][0], u1 = acc[mb][nb][1];
            float u2 = acc[mb][nb][2], u3 = acc[mb][nb][3];
            s0 += u0 + u1;  ss0 += u0 * u0 + u1 * u1;
            s1 += u2 + u3;  ss1 += u2 * u2 + u3 * u3;
        }
        #pragma unroll
        for (int m = 1; m < 4; m <<= 1) {
            s0  += __shfl_xor_sync(0xffffffffu, s0,  m);
            ss0 += __shfl_xor_sync(0xffffffffu, ss0, m);
            s1  += __shfl_xor_sync(0xffffffffu, s1,  m);
            ss1 += __shfl_xor_sync(0xffffffffu, ss1, m);
        }
        if (t == 0) {
            int e0 = mrow + mb * 16 + g;
            part[e0 * 4 + wN]       = make_float2(s0, ss0);
            part[(e0 + 8) * 4 + wN] = make_float2(s1, ss1);
        }
    }
    __syncthreads();

    if (tid < TILE) {
        float s = 0.f, ss = 0.f;
        #pragma unroll
        for (int q = 0; q < 4; ++q) {
            float2 p = part[tid * 4 + q];
            s += p.x; ss += p.y;
        }
        float mu  = s * (1.f / 128.f);
        float var = ss * (1.f / 128.f) - mu * mu;
        stats[tid] = make_float2(mu, rsqrtf(var + LN_EPS));
    }
    __syncthreads();

    #pragma unroll
    for (int mb = 0; mb < 2; ++mb) {
        const int r0 = mrow + mb * 16 + g;
        const float2 st0 = stats[r0];
        const float2 st1 = stats[r0 + 8];
        const int eg0 = e_base + r0;
        const int eg1 = eg0 + 8;
        #pragma unroll
        for (int nb = 0; nb < 4; ++nb) {
            const int c0 = ncol + nb * 8 + 2 * t;
            const float gm0 = sm[F_GM + c0], gm1 = sm[F_GM + c0 + 1];
            const float bt0 = sm[F_BT + c0], bt1 = sm[F_BT + c0 + 1];
            if (eg0 < n_edges) {
                float2 ef = *(const float2*)&in_s[r0 * S_IN + HD + c0];
                float2 o;
                o.x = ef.x + (acc[mb][nb][0] - st0.x) * st0.y * gm0 + bt0;
                o.y = ef.y + (acc[mb][nb][1] - st0.x) * st0.y * gm1 + bt1;
                *(float2*)&out[(long long)eg0 * HD + c0] = o;
            }
            if (eg1 < n_edges) {
                float2 ef = *(const float2*)&in_s[(r0 + 8) * S_IN + HD + c0];
                float2 o;
                o.x = ef.x + (acc[mb][nb][2] - st1.x) * st1.y * gm0 + bt0;
                o.y = ef.y + (acc[mb][nb][3] - st1.x) * st1.y * gm1 + bt1;
                *(float2*)&out[(long long)eg1 * HD + c0] = o;
            }
        }
    }
}

extern "C" void kernel_launch(void* const* d_in, const int* in_sizes, int n_in,
                              void* d_out, int out_size)
{
    const float* node_inv      = (const float*)d_in[0];
    const float* edge_features = (const float*)d_in[1];
    const void*  edge_src      = d_in[2];
    const void*  edge_dst      = d_in[3];
    const float* W1            = (const float*)d_in[4];
    const float* b1            = (const float*)d_in[5];
    const float* W2            = (const float*)d_in[6];
    const float* b2            = (const float*)d_in[7];
    const float* gamma         = (const float*)d_in[8];
    const float* beta          = (const float*)d_in[9];
    float* out = (float*)d_out;

    int n_edges = in_sizes[1] / HD;

    prep_w<<<(49152 + 255) / 256, 256>>>(W1, W2);

    int smem_bytes = SMEM_FLOATS * (int)sizeof(float);
    cudaFuncSetAttribute(edge_update_mma,
                         cudaFuncAttributeMaxDynamicSharedMemorySize, smem_bytes);

    int grid = (n_edges + TILE - 1) / TILE;
    edge_update_mma<<<grid, THREADS, smem_bytes>>>(
        node_inv, edge_features, edge_src, edge_dst,
        b1, b2, gamma, beta, out, n_edges);
}

// round 9
// speedup vs baseline: 5.3524x; 1.0444x over previous
#include <cuda_runtime.h>
#include <cuda_bf16.h>
#include <cstdint>

// ============================================================================
// EdgeUpdate, round 8: R7 with the W-double-buffer WAR race fixed
// (stage(ch+1) moved AFTER the wait+barrier, wait-group ledger re-derived).
//  - mma.sync m16n8k8 tf32, 512 threads, tile 128 edges x 128 ch, warp 32x32
//  - prep kernel stores W1^T / W2^T (channel-major [c][k]), tf32-rna-rounded
//  - W chunks (KC=64) cp.async double-buffered, stride 68
//  - gather: node part (K0-127) and ef part (K128-255) in separate groups
//  - A/B fragments via ldmatrix.m8n8.x4.b16, ks-level ping-pong prefetch
//  - h = relu(D1+b1) rna-rounded, overwrites in_s cols 0..127
//  - epilogue: +b2, per-edge LayerNorm, residual from exact fp32 ef in smem
// ============================================================================

#define THREADS   512
#define TILE      128
#define HD        128
#define KC        64
#define LN_EPS    1e-5f
#define S_IN      260       // in_s row stride (floats)
#define S_WT      68        // transposed W chunk row stride (floats)

// smem float offsets
#define F_IN      0
#define F_WBUF    (128 * S_IN)                   // 33280
#define F_PART    (F_WBUF + 2 * 128 * S_WT)      // 50688 (float2[128][4]) / idx alias
#define F_STATS   (F_PART + 128 * 4 * 2)         // 51712 (float2[128])
#define F_B1      (F_STATS + 256)
#define F_B2      (F_B1 + 128)
#define F_GM      (F_B2 + 128)
#define F_BT      (F_GM + 128)
#define SMEM_FLOATS (F_BT + 128)                 // 52480 floats = 209920 B

__device__ float g_Wt[49152];   // W1^T [128][256] ++ W2^T [128][128], tf32-rounded

__device__ __forceinline__ uint32_t tf32r(float x) {
    uint32_t r;
    asm("cvt.rna.tf32.f32 %0, %1;" : "=r"(r) : "f"(x));
    return r;
}
__device__ __forceinline__ float tf32rf(float x) { return __uint_as_float(tf32r(x)); }

__device__ __forceinline__ void mma8(float* d, const uint32_t* a, const uint32_t* b) {
    asm volatile(
        "mma.sync.aligned.m16n8k8.row.col.f32.tf32.tf32.f32 "
        "{%0,%1,%2,%3}, {%4,%5,%6,%7}, {%8,%9}, {%0,%1,%2,%3};"
        : "+f"(d[0]), "+f"(d[1]), "+f"(d[2]), "+f"(d[3])
        : "r"(a[0]), "r"(a[1]), "r"(a[2]), "r"(a[3]), "r"(b[0]), "r"(b[1]));
}

#define LDSM4(r, addr)                                                          \
    asm volatile("ldmatrix.sync.aligned.m8n8.x4.shared.b16 {%0,%1,%2,%3}, [%4];"\
        : "=r"((r)[0]), "=r"((r)[1]), "=r"((r)[2]), "=r"((r)[3]) : "r"(addr))

__device__ __forceinline__ uint32_t smem_u32(const void* p) {
    uint32_t a;
    asm("{ .reg .u64 t; cvta.to.shared.u64 t, %1; cvt.u32.u64 %0, t; }" : "=r"(a) : "l"(p));
    return a;
}
__device__ __forceinline__ void cp16(uint32_t dst, const void* src) {
    asm volatile("cp.async.cg.shared.global [%0], [%1], 16;" :: "r"(dst), "l"(src));
}
#define CP_COMMIT() asm volatile("cp.async.commit_group;" ::: "memory")
#define CP_WAIT(N)  asm volatile("cp.async.wait_group %0;" :: "n"(N) : "memory")

__global__ void prep_w(const float* __restrict__ W1, const float* __restrict__ W2) {
    int i = blockIdx.x * blockDim.x + threadIdx.x;      // i = c*K + k
    if (i < 32768) {
        int c = i >> 8, k = i & 255;
        g_Wt[i] = tf32rf(W1[k * HD + c]);
    } else if (i < 49152) {
        int j = i - 32768;
        int c = j >> 7, k = j & 127;
        g_Wt[i] = tf32rf(W2[k * HD + c]);
    }
}

__global__ __launch_bounds__(THREADS, 1)
void edge_update_mma(const float* __restrict__ node_inv,
                     const float* __restrict__ edge_features,
                     const void*  __restrict__ edge_src,
                     const void*  __restrict__ edge_dst,
                     const float* __restrict__ b1,
                     const float* __restrict__ b2,
                     const float* __restrict__ gamma,
                     const float* __restrict__ beta,
                     float* __restrict__ out,
                     int n_edges)
{
    extern __shared__ float sm[];
    float*  in_s  = sm + F_IN;
    float*  wbuf  = sm + F_WBUF;
    float2* part  = (float2*)(sm + F_PART);
    float2* stats = (float2*)(sm + F_STATS);
    int*    idxs  = (int*)(sm + F_PART);       // alias: used only during gather

    const uint32_t inb  = smem_u32(in_s);
    const uint32_t wbb  = smem_u32(wbuf);

    const int tid  = threadIdx.x;
    const int wid  = tid >> 5;
    const int lane = tid & 31;
    const int g    = lane >> 2;
    const int t    = lane & 3;
    const int mrow = (wid >> 2) * 32;
    const int ncol = (wid & 3) * 32;
    const int wN   = wid & 3;

    const int e_base = blockIdx.x * TILE;

    // index dtype sniff (int64 buffers have zero high words)
    const int* s32c = (const int*)edge_src;
    const bool idx64 = ((s32c[1] | s32c[3] | s32c[5] | s32c[7]) == 0);

    // ---- W chunk staging: 128 channel rows x KC floats = 2048 x 16B ----
    auto stage = [&](int ch) {
        const float* src;
        int kA, kstr;
        if (ch < 4) { src = g_Wt;         kA = ch * KC;       kstr = 256; }
        else        { src = g_Wt + 32768; kA = (ch - 4) * KC; kstr = 128; }
        uint32_t dstb = wbb + (uint32_t)((ch & 1) * 128 * S_WT) * 4u;
        #pragma unroll
        for (int i = 0; i < 4; ++i) {
            int idx = tid + i * THREADS;   // 0..2047
            int c   = idx >> 4;            // channel row 0..127
            int q   = idx & 15;            // 4-float quad 0..15
            cp16(dstb + (uint32_t)(c * S_WT + q * 4) * 4u,
                 src + c * kstr + kA + q * 4);
        }
        CP_COMMIT();
    };
    stage(0);                               // group: s0

    // small constants
    if (tid < 128) {
        sm[F_B1 + tid] = b1[tid];
        sm[F_B2 + tid] = b2[tid];
        sm[F_GM + tid] = gamma[tid];
        sm[F_BT + tid] = beta[tid];
    }

    // ---- stage edge indices (low words work for both int32/int64) ----
    if (tid < 256) {
        int e  = tid & 127;
        int eg = e_base + e;
        if (eg >= n_edges) eg = n_edges - 1;
        const int* p = (const int*)((tid < 128) ? edge_src : edge_dst);
        idxs[tid] = idx64 ? p[2 * eg] : p[eg];
    }
    __syncthreads();

    // ---- gather group A: node features, K cols 0..127 (j quads 0..31) ----
    #pragma unroll
    for (int it = 0; it < 8; ++it) {
        int q = tid + it * THREADS;          // 0..4095
        int e = q >> 5;
        int j = q & 31;
        int node = idxs[(j < 16 ? 0 : 128) + e];
        cp16(inb + (uint32_t)(e * S_IN + j * 4) * 4u,
             node_inv + (long long)node * 64 + (j & 15) * 4);
    }
    CP_COMMIT();                             // group: gA

    // ---- gather group B: edge_features, K cols 128..255 (j quads 32..63) ----
    {
        int eg_max = n_edges - 1;
        #pragma unroll
        for (int it = 0; it < 8; ++it) {
            int q = tid + it * THREADS;
            int e = q >> 5;
            int j = 32 + (q & 31);
            int eg = e_base + e; if (eg > eg_max) eg = eg_max;
            cp16(inb + (uint32_t)(e * S_IN + j * 4) * 4u,
                 edge_features + (long long)eg * HD + (j - 32) * 4);
        }
        CP_COMMIT();                         // group: gB
    }

    stage(1);                                // group: s1

    // per-lane static ldmatrix offsets (bytes)
    const uint32_t a_off = (uint32_t)((mrow + (lane & 7) + ((lane >> 3) & 1) * 8) * S_IN
                                      + ((lane >> 4) & 1) * 4) * 4u;
    const uint32_t b_off = (uint32_t)((ncol + (lane & 7) + ((lane >> 4) & 1) * 8) * S_WT
                                      + ((lane >> 3) & 1) * 4) * 4u;

    float acc[2][4][4];
    #pragma unroll
    for (int mb = 0; mb < 2; ++mb)
        #pragma unroll
        for (int nb = 0; nb < 4; ++nb)
            #pragma unroll
            for (int r = 0; r < 4; ++r) acc[mb][nb][r] = 0.f;

    // ---- mainloop: 6 chunks of K=64 (4 GEMM1, 2 GEMM2) ----
    // Wait ledger (stage committed AFTER the sync each iteration):
    //  ch0: pending {s0,gA,gB,s1} -> wait(2) drains s0,gA        (needs s0,gA)
    //  ch1: pending {gB,s1,s2}    -> wait(1) drains gB,s1        (needs s1)
    //  ch2: pending {s2,s3}       -> wait(1) drains s2           (needs gB,s2)
    //  ch3: pending {s3,s4}       -> wait(1) drains s3           (needs s3)
    //  ch4: pending {s4,s5}       -> wait(1) drains s4           (needs s4)
    //  ch5: pending {s5}          -> wait(0)                     (needs s5)
    #pragma unroll 1
    for (int ch = 0; ch < 6; ++ch) {
        if (ch == 0)      CP_WAIT(2);
        else if (ch < 5)  CP_WAIT(1);
        else              CP_WAIT(0);
        __syncthreads();                     // all readers of the dead buffer done
        if (ch >= 1 && ch < 5) stage(ch + 1);   // safe: write target last read 2 chunks ago

        const uint32_t wchunk = wbb + (uint32_t)((ch & 1) * 128 * S_WT) * 4u;
        const int kA = (ch < 4) ? ch * KC : (ch - 4) * KC;
        const uint32_t abase = inb + a_off + (uint32_t)kA * 4u;
        const uint32_t bbase = wchunk + b_off;

        // ks-level software pipeline (ping-pong fragment buffers)
        uint32_t a[2][2][4], b[2][2][4];
        LDSM4(a[0][0], abase);
        LDSM4(a[0][1], abase + (uint32_t)(16 * S_IN) * 4u);
        LDSM4(b[0][0], bbase);
        LDSM4(b[0][1], bbase + (uint32_t)(16 * S_WT) * 4u);

        #pragma unroll
        for (int ks = 0; ks < 8; ++ks) {
            const int cur = ks & 1, nxt = cur ^ 1;
            if (ks < 7) {
                const uint32_t k1b = (uint32_t)((ks + 1) * 8) * 4u;
                LDSM4(a[nxt][0], abase + k1b);
                LDSM4(a[nxt][1], abase + (uint32_t)(16 * S_IN) * 4u + k1b);
                LDSM4(b[nxt][0], bbase + k1b);
                LDSM4(b[nxt][1], bbase + (uint32_t)(16 * S_WT) * 4u + k1b);
            }
            #pragma unroll
            for (int mb = 0; mb < 2; ++mb) {
                mma8(acc[mb][0], a[cur][mb], b[cur][0]);
                mma8(acc[mb][1], a[cur][mb], b[cur][0] + 2);
                mma8(acc[mb][2], a[cur][mb], b[cur][1]);
                mma8(acc[mb][3], a[cur][mb], b[cur][1] + 2);
            }
        }

        if (ch == 3) {
            // h = relu(D1 + b1), rna tf32, into in_s cols 0..127
            #pragma unroll
            for (int mb = 0; mb < 2; ++mb) {
                const int r0 = mrow + mb * 16 + g;
                #pragma unroll
                for (int nb = 0; nb < 4; ++nb) {
                    const int c0 = ncol + nb * 8 + 2 * t;
                    const float bb0 = sm[F_B1 + c0], bb1 = sm[F_B1 + c0 + 1];
                    float2 h0, h1;
                    h0.x = tf32rf(fmaxf(acc[mb][nb][0] + bb0, 0.f));
                    h0.y = tf32rf(fmaxf(acc[mb][nb][1] + bb1, 0.f));
                    h1.x = tf32rf(fmaxf(acc[mb][nb][2] + bb0, 0.f));
                    h1.y = tf32rf(fmaxf(acc[mb][nb][3] + bb1, 0.f));
                    *(float2*)&in_s[r0 * S_IN + c0]       = h0;
                    *(float2*)&in_s[(r0 + 8) * S_IN + c0] = h1;
                }
            }
            #pragma unroll
            for (int mb = 0; mb < 2; ++mb)
                #pragma unroll
                for (int nb = 0; nb < 4; ++nb)
                    #pragma unroll
                    for (int r = 0; r < 4; ++r) acc[mb][nb][r] = 0.f;
            // next-iteration top __syncthreads orders h-store vs GEMM2 reads
        }
    }

    // ---- epilogue: u = D2 + b2; LayerNorm; residual; store ----
    #pragma unroll
    for (int mb = 0; mb < 2; ++mb)
        #pragma unroll
        for (int nb = 0; nb < 4; ++nb) {
            const int c0 = ncol + nb * 8 + 2 * t;
            acc[mb][nb][0] += sm[F_B2 + c0];
            acc[mb][nb][1] += sm[F_B2 + c0 + 1];
            acc[mb][nb][2] += sm[F_B2 + c0];
            acc[mb][nb][3] += sm[F_B2 + c0 + 1];
        }

    __syncthreads();   // idxs alias dead; part now safe to write

    #pragma unroll
    for (int mb = 0; mb < 2; ++mb) {
        float s0 = 0.f, ss0 = 0.f, s1 = 0.f, ss1 = 0.f;
        #pragma unroll
        for (int nb = 0; nb < 4; ++nb) {
            float u0 = acc[mb][nb][0], u1 = acc[mb][nb][1];
            float u2 = acc[mb][nb][2], u3 = acc[mb][nb][3];
            s0 += u0 + u1;  ss0 += u0 * u0 + u1 * u1;
            s1 += u2 + u3;  ss1 += u2 * u2 + u3 * u3;
        }
        #pragma unroll
        for (int m = 1; m < 4; m <<= 1) {
            s0  += __shfl_xor_sync(0xffffffffu, s0,  m);
            ss0 += __shfl_xor_sync(0xffffffffu, ss0, m);
            s1  += __shfl_xor_sync(0xffffffffu, s1,  m);
            ss1 += __shfl_xor_sync(0xffffffffu, ss1, m);
        }
        if (t == 0) {
            int e0 = mrow + mb * 16 + g;
            part[e0 * 4 + wN]       = make_float2(s0, ss0);
            part[(e0 + 8) * 4 + wN] = make_float2(s1, ss1);
        }
    }
    __syncthreads();

    if (tid < TILE) {
        float s = 0.f, ss = 0.f;
        #pragma unroll
        for (int q = 0; q < 4; ++q) {
            float2 p = part[tid * 4 + q];
            s += p.x; ss += p.y;
        }
        float mu  = s * (1.f / 128.f);
        float var = ss * (1.f / 128.f) - mu * mu;
        stats[tid] = make_float2(mu, rsqrtf(var + LN_EPS));
    }
    __syncthreads();

    #pragma unroll
    for (int mb = 0; mb < 2; ++mb) {
        const int r0 = mrow + mb * 16 + g;
        const float2 st0 = stats[r0];
        const float2 st1 = stats[r0 + 8];
        const int eg0 = e_base + r0;
        const int eg1 = eg0 + 8;
        #pragma unroll
        for (int nb = 0; nb < 4; ++nb) {
            const int c0 = ncol + nb * 8 + 2 * t;
            const float gm0 = sm[F_GM + c0], gm1 = sm[F_GM + c0 + 1];
            const float bt0 = sm[F_BT + c0], bt1 = sm[F_BT + c0 + 1];
            if (eg0 < n_edges) {
                float2 ef = *(const float2*)&in_s[r0 * S_IN + HD + c0];
                float2 o;
                o.x = ef.x + (acc[mb][nb][0] - st0.x) * st0.y * gm0 + bt0;
                o.y = ef.y + (acc[mb][nb][1] - st0.x) * st0.y * gm1 + bt1;
                *(float2*)&out[(long long)eg0 * HD + c0] = o;
            }
            if (eg1 < n_edges) {
                float2 ef = *(const float2*)&in_s[(r0 + 8) * S_IN + HD + c0];
                float2 o;
                o.x = ef.x + (acc[mb][nb][2] - st1.x) * st1.y * gm0 + bt0;
                o.y = ef.y + (acc[mb][nb][3] - st1.x) * st1.y * gm1 + bt1;
                *(float2*)&out[(long long)eg1 * HD + c0] = o;
            }
        }
    }
}

extern "C" void kernel_launch(void* const* d_in, const int* in_sizes, int n_in,
                              void* d_out, int out_size)
{
    const float* node_inv      = (const float*)d_in[0];
    const float* edge_features = (const float*)d_in[1];
    const void*  edge_src      = d_in[2];
    const void*  edge_dst      = d_in[3];
    const float* W1            = (const float*)d_in[4];
    const float* b1            = (const float*)d_in[5];
    const float* W2            = (const float*)d_in[6];
    const float* b2            = (const float*)d_in[7];
    const float* gamma         = (const float*)d_in[8];
    const float* beta          = (const float*)d_in[9];
    float* out = (float*)d_out;

    int n_edges = in_sizes[1] / HD;

    prep_w<<<(49152 + 255) / 256, 256>>>(W1, W2);

    int smem_bytes = SMEM_FLOATS * (int)sizeof(float);
    cudaFuncSetAttribute(edge_update_mma,
                         cudaFuncAttributeMaxDynamicSharedMemorySize, smem_bytes);

    int grid = (n_edges + TILE - 1) / TILE;
    edge_update_mma<<<grid, THREADS, smem_bytes>>>(
        node_inv, edge_features, edge_src, edge_dst,
        b1, b2, gamma, beta, out, n_edges);
}

// round 11
// speedup vs baseline: 6.8370x; 1.2774x over previous
#include <cuda_runtime.h>
#include <cuda_fp16.h>
#include <cstdint>

// ============================================================================
// EdgeUpdate, round 10: fp16 m16n8k16 MMA (fp32 accumulate). R9 with the
// __half2_as_uint compile error fixed (direct __half2 stores).
//  - prep kernels: node_inv -> fp16 g_ni16; W1^T/W2^T -> fp16 g_Wt16
//  - A16 smem [128 e][264 halfs]: cols 0-127 node halfs (cp.async from g_ni16),
//    cols 128-255 ef (converted in-kernel from fp32 ef_s)
//  - ef_s [128][132] fp32 keeps exact edge_features for the residual
//  - W chunks (64 K-halfs x 128 ch) cp.async double-buffered, stride 72 halfs
//  - fragments via ldmatrix.m8n8.x4.b16; ks-pipeline; 6 chunks (4 GEMM1+2 GEMM2)
//  - h = relu(D1+b1) -> fp16 into A16 cols 0-127; epilogue LN fp32 + residual
// ============================================================================

#define THREADS   512
#define TILE      128
#define HD        128
#define LN_EPS    1e-5f
#define S_A       264     // A16 row stride (halfs)
#define S_W       72      // W chunk row stride (halfs)
#define S_EF      132     // ef_s row stride (floats)

// smem byte offsets
#define O_A16    0
#define O_W16    67584                    // 128*264*2
#define O_EFS    (O_W16 + 36864)          // 2*128*72*2 -> 104448
#define O_PART   (O_EFS + 67584)          // 172032 (float2[128][4]) / idxs alias
#define O_STATS  (O_PART + 4096)          // 176128 (float2[128])
#define O_B1     (O_STATS + 1024)         // 177152
#define O_B2     (O_B1 + 512)
#define O_GM     (O_B2 + 512)
#define O_BT     (O_GM + 512)
#define SMEM_BYTES (O_BT + 512)           // 179200

__device__ __half g_ni16[50000 * 64];     // node_inv in fp16
__device__ __half g_Wt16[49152];          // W1^T [128][256] ++ W2^T [128][128]

__device__ __forceinline__ void mma16(float* d, const uint32_t* a,
                                      uint32_t b0, uint32_t b1) {
    asm volatile(
        "mma.sync.aligned.m16n8k16.row.col.f32.f16.f16.f32 "
        "{%0,%1,%2,%3}, {%4,%5,%6,%7}, {%8,%9}, {%0,%1,%2,%3};"
        : "+f"(d[0]), "+f"(d[1]), "+f"(d[2]), "+f"(d[3])
        : "r"(a[0]), "r"(a[1]), "r"(a[2]), "r"(a[3]), "r"(b0), "r"(b1));
}

#define LDSM4(r, addr)                                                          \
    asm volatile("ldmatrix.sync.aligned.m8n8.x4.shared.b16 {%0,%1,%2,%3}, [%4];"\
        : "=r"((r)[0]), "=r"((r)[1]), "=r"((r)[2]), "=r"((r)[3]) : "r"(addr))

__device__ __forceinline__ uint32_t smem_u32(const void* p) {
    uint32_t a;
    asm("{ .reg .u64 t; cvta.to.shared.u64 t, %1; cvt.u32.u64 %0, t; }" : "=r"(a) : "l"(p));
    return a;
}
__device__ __forceinline__ void cp16(uint32_t dst, const void* src) {
    asm volatile("cp.async.cg.shared.global [%0], [%1], 16;" :: "r"(dst), "l"(src));
}
#define CP_COMMIT() asm volatile("cp.async.commit_group;" ::: "memory")
#define CP_WAIT(N)  asm volatile("cp.async.wait_group %0;" :: "n"(N) : "memory")

__global__ void prep_node(const float* __restrict__ node_inv, int n) {
    int i = blockIdx.x * blockDim.x + threadIdx.x;
    if (i < n) g_ni16[i] = __float2half_rn(node_inv[i]);
}
__global__ void prep_w(const float* __restrict__ W1, const float* __restrict__ W2) {
    int i = blockIdx.x * blockDim.x + threadIdx.x;      // i = c*K + k
    if (i < 32768) {
        int c = i >> 8, k = i & 255;
        g_Wt16[i] = __float2half_rn(W1[k * HD + c]);
    } else if (i < 49152) {
        int j = i - 32768;
        int c = j >> 7, k = j & 127;
        g_Wt16[i] = __float2half_rn(W2[k * HD + c]);
    }
}

__global__ __launch_bounds__(THREADS, 1)
void edge_update_mma(const float* __restrict__ edge_features,
                     const void*  __restrict__ edge_src,
                     const void*  __restrict__ edge_dst,
                     const float* __restrict__ b1,
                     const float* __restrict__ b2,
                     const float* __restrict__ gamma,
                     const float* __restrict__ beta,
                     float* __restrict__ out,
                     int n_edges)
{
    extern __shared__ char smc[];
    __half* A16   = (__half*)(smc + O_A16);
    float*  ef_s  = (float*)(smc + O_EFS);
    float2* part  = (float2*)(smc + O_PART);
    float2* stats = (float2*)(smc + O_STATS);
    int*    idxs  = (int*)(smc + O_PART);     // alias: gather phase only
    float*  cb1   = (float*)(smc + O_B1);
    float*  cb2   = (float*)(smc + O_B2);
    float*  cgm   = (float*)(smc + O_GM);
    float*  cbt   = (float*)(smc + O_BT);

    const uint32_t a16b = smem_u32(A16);
    const uint32_t wbb  = smem_u32(smc + O_W16);
    const uint32_t efb  = smem_u32(ef_s);

    const int tid  = threadIdx.x;
    const int wid  = tid >> 5;
    const int lane = tid & 31;
    const int g    = lane >> 2;
    const int t    = lane & 3;
    const int mrow = (wid >> 2) * 32;
    const int ncol = (wid & 3) * 32;
    const int wN   = wid & 3;

    const int e_base = blockIdx.x * TILE;

    // index dtype sniff (int64 buffers have zero high words)
    const int* s32c = (const int*)edge_src;
    const bool idx64 = ((s32c[1] | s32c[3] | s32c[5] | s32c[7]) == 0);

    // ---- W chunk staging: 128 rows x 64 halfs = 1024 x 16B ----
    auto stage = [&](int ch) {
        const __half* src;
        int kA, kstr;
        if (ch < 4) { src = g_Wt16;         kA = ch * 64;       kstr = 256; }
        else        { src = g_Wt16 + 32768; kA = (ch - 4) * 64; kstr = 128; }
        uint32_t dstb = wbb + (uint32_t)((ch & 1) * 128 * S_W) * 2u;
        #pragma unroll
        for (int i = 0; i < 2; ++i) {
            int idx = tid + i * THREADS;   // 0..1023
            int c   = idx >> 3;            // channel row
            int q   = idx & 7;             // 8-half quad
            cp16(dstb + (uint32_t)(c * S_W + q * 8) * 2u,
                 src + c * kstr + kA + q * 8);
        }
        CP_COMMIT();
    };
    stage(0);                               // group: s0

    if (tid < 128) {
        cb1[tid] = b1[tid];
        cb2[tid] = b2[tid];
        cgm[tid] = gamma[tid];
        cbt[tid] = beta[tid];
    }

    // ---- stage edge indices ----
    if (tid < 256) {
        int e  = tid & 127;
        int eg = e_base + e;
        if (eg >= n_edges) eg = n_edges - 1;
        const int* p = (const int*)((tid < 128) ? edge_src : edge_dst);
        idxs[tid] = idx64 ? p[2 * eg] : p[eg];
    }
    __syncthreads();

    // ---- gather group gA: node halfs -> A16 cols 0..127 (16B = 8 halfs) ----
    #pragma unroll
    for (int it = 0; it < 4; ++it) {
        int q = tid + it * THREADS;          // 0..2047
        int e = q >> 4;
        int j = q & 15;                      // 8-half quad: 0-7 src, 8-15 dst
        int node = idxs[(j < 8 ? 0 : 128) + e];
        cp16(a16b + (uint32_t)(e * S_A + j * 8) * 2u,
             g_ni16 + (long long)node * 64 + (j & 7) * 8);
    }
    CP_COMMIT();                             // group: gA

    // ---- gather group gB: edge_features fp32 -> ef_s ----
    {
        int eg_max = n_edges - 1;
        #pragma unroll
        for (int it = 0; it < 8; ++it) {
            int q = tid + it * THREADS;      // 0..4095
            int e = q >> 5;
            int j = q & 31;                  // 4-float quad
            int eg = e_base + e; if (eg > eg_max) eg = eg_max;
            cp16(efb + (uint32_t)(e * S_EF + j * 4) * 4u,
                 edge_features + (long long)eg * HD + j * 4);
        }
        CP_COMMIT();                         // group: gB
    }

    stage(1);                                // group: s1

    // per-lane static ldmatrix byte offsets
    const uint32_t a_off = (uint32_t)((mrow + (lane & 15)) * S_A + ((lane >> 4) & 1) * 8) * 2u;
    const uint32_t b_off = (uint32_t)((ncol + (lane & 15)) * S_W + ((lane >> 4) & 1) * 8) * 2u;

    float acc[2][4][4];
    #pragma unroll
    for (int mb = 0; mb < 2; ++mb)
        #pragma unroll
        for (int nb = 0; nb < 4; ++nb)
            #pragma unroll
            for (int r = 0; r < 4; ++r) acc[mb][nb][r] = 0.f;

    // Wait ledger (stage AFTER sync): ch0 wait(2) [s0,gA]; ch1 wait(1) [gB,s1];
    // ch2-4 wait(1); ch5 wait(0).
    #pragma unroll 1
    for (int ch = 0; ch < 6; ++ch) {
        if (ch == 0)      CP_WAIT(2);
        else if (ch < 5)  CP_WAIT(1);
        else              CP_WAIT(0);
        __syncthreads();
        if (ch >= 1 && ch < 5) stage(ch + 1);

        if (ch == 1) {
            // convert ef fp32 -> fp16 into A16 cols 128..255 (gB drained above)
            #pragma unroll
            for (int i = 0; i < 16; ++i) {
                int p = tid + i * THREADS;       // 0..8191 half2 units
                int e = p >> 6, c2 = p & 63;
                float2 v = *(const float2*)&ef_s[e * S_EF + 2 * c2];
                *(__half2*)&A16[e * S_A + 128 + 2 * c2] = __float22half2_rn(v);
            }
        }

        const uint32_t wchunk = wbb + (uint32_t)((ch & 1) * 128 * S_W) * 2u;
        const int kA = (ch < 4) ? ch * 64 : (ch - 4) * 64;   // halfs
        const uint32_t abase = a16b + a_off + (uint32_t)kA * 2u;
        const uint32_t bbase = wchunk + b_off;

        // ks-level software pipeline, K=16 per ks, 4 ks per chunk
        uint32_t a[2][2][4], b[2][2][4];
        LDSM4(a[0][0], abase);
        LDSM4(a[0][1], abase + (uint32_t)(16 * S_A) * 2u);
        LDSM4(b[0][0], bbase);
        LDSM4(b[0][1], bbase + (uint32_t)(16 * S_W) * 2u);

        #pragma unroll
        for (int ks = 0; ks < 4; ++ks) {
            const int cur = ks & 1, nxt = cur ^ 1;
            if (ks < 3) {
                const uint32_t k1b = (uint32_t)((ks + 1) * 16) * 2u;
                LDSM4(a[nxt][0], abase + k1b);
                LDSM4(a[nxt][1], abase + (uint32_t)(16 * S_A) * 2u + k1b);
                LDSM4(b[nxt][0], bbase + k1b);
                LDSM4(b[nxt][1], bbase + (uint32_t)(16 * S_W) * 2u + k1b);
            }
            #pragma unroll
            for (int mb = 0; mb < 2; ++mb) {
                mma16(acc[mb][0], a[cur][mb], b[cur][0][0], b[cur][0][2]);
                mma16(acc[mb][1], a[cur][mb], b[cur][0][1], b[cur][0][3]);
                mma16(acc[mb][2], a[cur][mb], b[cur][1][0], b[cur][1][2]);
                mma16(acc[mb][3], a[cur][mb], b[cur][1][1], b[cur][1][3]);
            }
        }

        if (ch == 3) {
            // h = relu(D1 + b1) -> fp16 into A16 cols 0..127
            // (cols 0..127 last read in ch1; ch4-top sync orders vs GEMM2 reads)
            #pragma unroll
            for (int mb = 0; mb < 2; ++mb) {
                const int r0 = mrow + mb * 16 + g;
                #pragma unroll
                for (int nb = 0; nb < 4; ++nb) {
                    const int c0 = ncol + nb * 8 + 2 * t;
                    const float bb0 = cb1[c0], bb1 = cb1[c0 + 1];
                    float2 h0 = make_float2(fmaxf(acc[mb][nb][0] + bb0, 0.f),
                                            fmaxf(acc[mb][nb][1] + bb1, 0.f));
                    float2 h1 = make_float2(fmaxf(acc[mb][nb][2] + bb0, 0.f),
                                            fmaxf(acc[mb][nb][3] + bb1, 0.f));
                    *(__half2*)&A16[r0 * S_A + c0]       = __float22half2_rn(h0);
                    *(__half2*)&A16[(r0 + 8) * S_A + c0] = __float22half2_rn(h1);
                }
            }
            #pragma unroll
            for (int mb = 0; mb < 2; ++mb)
                #pragma unroll
                for (int nb = 0; nb < 4; ++nb)
                    #pragma unroll
                    for (int r = 0; r < 4; ++r) acc[mb][nb][r] = 0.f;
        }
    }

    // ---- epilogue: u = D2 + b2; LayerNorm; residual; store ----
    #pragma unroll
    for (int mb = 0; mb < 2; ++mb)
        #pragma unroll
        for (int nb = 0; nb < 4; ++nb) {
            const int c0 = ncol + nb * 8 + 2 * t;
            acc[mb][nb][0] += cb2[c0];
            acc[mb][nb][1] += cb2[c0 + 1];
            acc[mb][nb][2] += cb2[c0];
            acc[mb][nb][3] += cb2[c0 + 1];
        }

    __syncthreads();   // idxs alias dead; part safe to write

    #pragma unroll
    for (int mb = 0; mb < 2; ++mb) {
        float s0 = 0.f, ss0 = 0.f, s1 = 0.f, ss1 = 0.f;
        #pragma unroll
        for (int nb = 0; nb < 4; ++nb) {
            float u0 = acc[mb][nb][0], u1 = acc[mb][nb][1];
            float u2 = acc[mb][nb][2], u3 = acc[mb][nb][3];
            s0 += u0 + u1;  ss0 += u0 * u0 + u1 * u1;
            s1 += u2 + u3;  ss1 += u2 * u2 + u3 * u3;
        }
        #pragma unroll
        for (int m = 1; m < 4; m <<= 1) {
            s0  += __shfl_xor_sync(0xffffffffu, s0,  m);
            ss0 += __shfl_xor_sync(0xffffffffu, ss0, m);
            s1  += __shfl_xor_sync(0xffffffffu, s1,  m);
            ss1 += __shfl_xor_sync(0xffffffffu, ss1, m);
        }
        if (t == 0) {
            int e0 = mrow + mb * 16 + g;
            part[e0 * 4 + wN]       = make_float2(s0, ss0);
            part[(e0 + 8) * 4 + wN] = make_float2(s1, ss1);
        }
    }
    __syncthreads();

    if (tid < TILE) {
        float s = 0.f, ss = 0.f;
        #pragma unroll
        for (int q = 0; q < 4; ++q) {
            float2 p = part[tid * 4 + q];
            s += p.x; ss += p.y;
        }
        float mu  = s * (1.f / 128.f);
        float var = ss * (1.f / 128.f) - mu * mu;
        stats[tid] = make_float2(mu, rsqrtf(var + LN_EPS));
    }
    __syncthreads();

    #pragma unroll
    for (int mb = 0; mb < 2; ++mb) {
        const int r0 = mrow + mb * 16 + g;
        const float2 st0 = stats[r0];
        const float2 st1 = stats[r0 + 8];
        const int eg0 = e_base + r0;
        const int eg1 = eg0 + 8;
        #pragma unroll
        for (int nb = 0; nb < 4; ++nb) {
            const int c0 = ncol + nb * 8 + 2 * t;
            const float gm0 = cgm[c0], gm1 = cgm[c0 + 1];
            const float bt0 = cbt[c0], bt1 = cbt[c0 + 1];
            if (eg0 < n_edges) {
                float2 ef = *(const float2*)&ef_s[r0 * S_EF + c0];
                float2 o;
                o.x = ef.x + (acc[mb][nb][0] - st0.x) * st0.y * gm0 + bt0;
                o.y = ef.y + (acc[mb][nb][1] - st0.x) * st0.y * gm1 + bt1;
                *(float2*)&out[(long long)eg0 * HD + c0] = o;
            }
            if (eg1 < n_edges) {
                float2 ef = *(const float2*)&ef_s[(r0 + 8) * S_EF + c0];
                float2 o;
                o.x = ef.x + (acc[mb][nb][2] - st1.x) * st1.y * gm0 + bt0;
                o.y = ef.y + (acc[mb][nb][3] - st1.x) * st1.y * gm1 + bt1;
                *(float2*)&out[(long long)eg1 * HD + c0] = o;
            }
        }
    }
}

extern "C" void kernel_launch(void* const* d_in, const int* in_sizes, int n_in,
                              void* d_out, int out_size)
{
    const float* node_inv      = (const float*)d_in[0];
    const float* edge_features = (const float*)d_in[1];
    const void*  edge_src      = d_in[2];
    const void*  edge_dst      = d_in[3];
    const float* W1            = (const float*)d_in[4];
    const float* b1            = (const float*)d_in[5];
    const float* W2            = (const float*)d_in[6];
    const float* b2            = (const float*)d_in[7];
    const float* gamma         = (const float*)d_in[8];
    const float* beta          = (const float*)d_in[9];
    float* out = (float*)d_out;

    int n_edges = in_sizes[1] / HD;
    int n_node_elems = in_sizes[0];
    if (n_node_elems > 50000 * 64) n_node_elems = 50000 * 64;

    prep_node<<<(n_node_elems + 255) / 256, 256>>>(node_inv, n_node_elems);
    prep_w<<<(49152 + 255) / 256, 256>>>(W1, W2);

    cudaFuncSetAttribute(edge_update_mma,
                         cudaFuncAttributeMaxDynamicSharedMemorySize, SMEM_BYTES);

    int grid = (n_edges + TILE - 1) / TILE;
    edge_update_mma<<<grid, THREADS, SMEM_BYTES>>>(
        edge_features, edge_src, edge_dst,
        b1, b2, gamma, beta, out, n_edges);
}

// round 12
// speedup vs baseline: 8.6594x; 1.2665x over previous
#include <cuda_runtime.h>
#include <cuda_fp16.h>
#include <cstdint>

// ============================================================================
// EdgeUpdate, round 11: 2 CTAs/SM + 64x32 warp tiles.
//  - 256 threads/CTA, 8 warps, warp tile 64 edges x 32 channels
//  - smem 109 KB (A16 + W double-buffer only) -> 2 CTAs resident per SM
//  - node gather: cp.async from fp16 g_ni16; ef: LDG fp32 -> cvt -> STS fp16
//  - residual: exact fp32 edge_features re-read from gmem (L2-hot) in epilogue
//  - fragments via ldmatrix.m8n8.x4.b16; mma.m16n8k16.f32.f16
// ============================================================================

#define THREADS   256
#define TILE      128
#define HD        128
#define LN_EPS    1e-5f
#define S_A       264     // A16 row stride (halfs)
#define S_W       72      // W chunk row stride (halfs)

// smem byte offsets
#define O_A16    0
#define O_W16    67584                    // 128*264*2
#define O_PART   (O_W16 + 36864)          // 104448 (float2[128][4]) / idxs alias
#define O_STATS  (O_PART + 4096)          // 108544 (float2[128])
#define O_B1     (O_STATS + 1024)         // 109568
#define O_B2     (O_B1 + 512)
#define O_GM     (O_B2 + 512)
#define O_BT     (O_GM + 512)
#define SMEM_BYTES (O_BT + 512)           // 111616 (109 KB) -> 2 CTAs/SM

__device__ __half g_ni16[50000 * 64];     // node_inv in fp16
__device__ __half g_Wt16[49152];          // W1^T [128][256] ++ W2^T [128][128]

__device__ __forceinline__ void mma16(float* d, const uint32_t* a,
                                      uint32_t b0, uint32_t b1) {
    asm volatile(
        "mma.sync.aligned.m16n8k16.row.col.f32.f16.f16.f32 "
        "{%0,%1,%2,%3}, {%4,%5,%6,%7}, {%8,%9}, {%0,%1,%2,%3};"
        : "+f"(d[0]), "+f"(d[1]), "+f"(d[2]), "+f"(d[3])
        : "r"(a[0]), "r"(a[1]), "r"(a[2]), "r"(a[3]), "r"(b0), "r"(b1));
}

#define LDSM4(r, addr)                                                          \
    asm volatile("ldmatrix.sync.aligned.m8n8.x4.shared.b16 {%0,%1,%2,%3}, [%4];"\
        : "=r"((r)[0]), "=r"((r)[1]), "=r"((r)[2]), "=r"((r)[3]) : "r"(addr))

__device__ __forceinline__ uint32_t smem_u32(const void* p) {
    uint32_t a;
    asm("{ .reg .u64 t; cvta.to.shared.u64 t, %1; cvt.u32.u64 %0, t; }" : "=r"(a) : "l"(p));
    return a;
}
__device__ __forceinline__ void cp16(uint32_t dst, const void* src) {
    asm volatile("cp.async.cg.shared.global [%0], [%1], 16;" :: "r"(dst), "l"(src));
}
#define CP_COMMIT() asm volatile("cp.async.commit_group;" ::: "memory")
#define CP_WAIT(N)  asm volatile("cp.async.wait_group %0;" :: "n"(N) : "memory")

__global__ void prep_node(const float* __restrict__ node_inv, int n) {
    int i = blockIdx.x * blockDim.x + threadIdx.x;
    if (i < n) g_ni16[i] = __float2half_rn(node_inv[i]);
}
__global__ void prep_w(const float* __restrict__ W1, const float* __restrict__ W2) {
    int i = blockIdx.x * blockDim.x + threadIdx.x;      // i = c*K + k
    if (i < 32768) {
        int c = i >> 8, k = i & 255;
        g_Wt16[i] = __float2half_rn(W1[k * HD + c]);
    } else if (i < 49152) {
        int j = i - 32768;
        int c = j >> 7, k = j & 127;
        g_Wt16[i] = __float2half_rn(W2[k * HD + c]);
    }
}

__global__ __launch_bounds__(THREADS, 2)
void edge_update_mma(const float* __restrict__ edge_features,
                     const void*  __restrict__ edge_src,
                     const void*  __restrict__ edge_dst,
                     const float* __restrict__ b1,
                     const float* __restrict__ b2,
                     const float* __restrict__ gamma,
                     const float* __restrict__ beta,
                     float* __restrict__ out,
                     int n_edges)
{
    extern __shared__ char smc[];
    __half* A16   = (__half*)(smc + O_A16);
    float2* part  = (float2*)(smc + O_PART);
    float2* stats = (float2*)(smc + O_STATS);
    int*    idxs  = (int*)(smc + O_PART);     // alias: gather phase only
    float*  cb1   = (float*)(smc + O_B1);
    float*  cb2   = (float*)(smc + O_B2);
    float*  cgm   = (float*)(smc + O_GM);
    float*  cbt   = (float*)(smc + O_BT);

    const uint32_t a16b = smem_u32(A16);
    const uint32_t wbb  = smem_u32(smc + O_W16);

    const int tid  = threadIdx.x;
    const int wid  = tid >> 5;
    const int lane = tid & 31;
    const int g    = lane >> 2;
    const int t    = lane & 3;
    const int mrow = (wid >> 2) * 64;     // 2 M-halves
    const int ncol = (wid & 3) * 32;      // 4 N-quarters
    const int wN   = wid & 3;

    const int e_base = blockIdx.x * TILE;

    // index dtype sniff (int64 buffers have zero high words)
    const int* s32c = (const int*)edge_src;
    const bool idx64 = ((s32c[1] | s32c[3] | s32c[5] | s32c[7]) == 0);

    // ---- W chunk staging: 128 rows x 64 halfs = 1024 x 16B ----
    auto stage = [&](int ch) {
        const __half* src;
        int kA, kstr;
        if (ch < 4) { src = g_Wt16;         kA = ch * 64;       kstr = 256; }
        else        { src = g_Wt16 + 32768; kA = (ch - 4) * 64; kstr = 128; }
        uint32_t dstb = wbb + (uint32_t)((ch & 1) * 128 * S_W) * 2u;
        #pragma unroll
        for (int i = 0; i < 4; ++i) {
            int idx = tid + i * THREADS;   // 0..1023
            int c   = idx >> 3;            // channel row
            int q   = idx & 7;             // 8-half quad
            cp16(dstb + (uint32_t)(c * S_W + q * 8) * 2u,
                 src + c * kstr + kA + q * 8);
        }
        CP_COMMIT();
    };
    stage(0);                               // group: s0

    if (tid < 128) {
        cb1[tid] = b1[tid];
        cb2[tid] = b2[tid];
        cgm[tid] = gamma[tid];
        cbt[tid] = beta[tid];
    }

    // ---- stage edge indices ----
    {
        int e  = tid & 127;
        int eg = e_base + e;
        if (eg >= n_edges) eg = n_edges - 1;
        const int* p = (const int*)((tid < 128) ? edge_src : edge_dst);
        idxs[tid] = idx64 ? p[2 * eg] : p[eg];
    }
    __syncthreads();

    // ---- gather gA: node halfs -> A16 cols 0..127 (16B = 8 halfs) ----
    #pragma unroll
    for (int it = 0; it < 8; ++it) {
        int q = tid + it * THREADS;          // 0..2047
        int e = q >> 4;
        int j = q & 15;                      // 8-half quad: 0-7 src, 8-15 dst
        int node = idxs[(j < 8 ? 0 : 128) + e];
        cp16(a16b + (uint32_t)(e * S_A + j * 8) * 2u,
             g_ni16 + (long long)node * 64 + (j & 7) * 8);
    }
    CP_COMMIT();                             // group: gA

    stage(1);                                // group: s1

    // ---- ef: LDG fp32 -> cvt -> STS fp16 into A16 cols 128..255 ----
    {
        int eg_max = n_edges - 1;
        #pragma unroll 4
        for (int it = 0; it < 16; ++it) {
            int q = tid + it * THREADS;      // 0..4095
            int e = q >> 5;
            int j = q & 31;                  // 4-float quad
            int eg = e_base + e; if (eg > eg_max) eg = eg_max;
            float4 v = *(const float4*)(edge_features + (long long)eg * HD + j * 4);
            __half2 h01 = __floats2half2_rn(v.x, v.y);
            __half2 h23 = __floats2half2_rn(v.z, v.w);
            *(__half2*)&A16[e * S_A + 128 + j * 4]     = h01;
            *(__half2*)&A16[e * S_A + 128 + j * 4 + 2] = h23;
        }
    }

    // per-lane static ldmatrix byte offsets
    const uint32_t a_off = (uint32_t)((mrow + (lane & 15)) * S_A + ((lane >> 4) & 1) * 8) * 2u;
    const uint32_t b_off = (uint32_t)((ncol + (lane & 15)) * S_W + ((lane >> 4) & 1) * 8) * 2u;

    float acc[4][4][4];
    #pragma unroll
    for (int mb = 0; mb < 4; ++mb)
        #pragma unroll
        for (int nb = 0; nb < 4; ++nb)
            #pragma unroll
            for (int r = 0; r < 4; ++r) acc[mb][nb][r] = 0.f;

    // Wait ledger (stage AFTER sync):
    //  ch0: pending {s0,gA,s1} -> wait(1) drains s0,gA (needs s0,gA; ef STS is
    //       plain-store, ordered by this thread + ch2-top sync for other warps)
    //  ch1: pending {s1,s2} -> wait(1) drains s1
    //  ch2-4: wait(1);  ch5: wait(0)
    #pragma unroll 1
    for (int ch = 0; ch < 6; ++ch) {
        if (ch < 5)  CP_WAIT(1);
        else         CP_WAIT(0);
        __syncthreads();
        if (ch >= 1 && ch < 5) stage(ch + 1);

        const uint32_t wchunk = wbb + (uint32_t)((ch & 1) * 128 * S_W) * 2u;
        const int kA = (ch < 4) ? ch * 64 : (ch - 4) * 64;   // halfs
        const uint32_t abase = a16b + a_off + (uint32_t)kA * 2u;
        const uint32_t bbase = wchunk + b_off;

        #pragma unroll
        for (int ks = 0; ks < 4; ++ks) {
            const uint32_t kb = (uint32_t)(ks * 16) * 2u;
            uint32_t a[4][4], b[2][4];
            LDSM4(a[0], abase + kb);
            LDSM4(a[1], abase + (uint32_t)(16 * S_A) * 2u + kb);
            LDSM4(a[2], abase + (uint32_t)(32 * S_A) * 2u + kb);
            LDSM4(a[3], abase + (uint32_t)(48 * S_A) * 2u + kb);
            LDSM4(b[0], bbase + kb);
            LDSM4(b[1], bbase + (uint32_t)(16 * S_W) * 2u + kb);
            #pragma unroll
            for (int mb = 0; mb < 4; ++mb) {
                mma16(acc[mb][0], a[mb], b[0][0], b[0][2]);
                mma16(acc[mb][1], a[mb], b[0][1], b[0][3]);
                mma16(acc[mb][2], a[mb], b[1][0], b[1][2]);
                mma16(acc[mb][3], a[mb], b[1][1], b[1][3]);
            }
        }

        if (ch == 3) {
            // h = relu(D1 + b1) -> fp16 into A16 cols 0..127
            // (cols 0..127 last read at ch1; ch4-top sync orders vs GEMM2 reads)
            #pragma unroll
            for (int mb = 0; mb < 4; ++mb) {
                const int r0 = mrow + mb * 16 + g;
                #pragma unroll
                for (int nb = 0; nb < 4; ++nb) {
                    const int c0 = ncol + nb * 8 + 2 * t;
                    const float bb0 = cb1[c0], bb1 = cb1[c0 + 1];
                    *(__half2*)&A16[r0 * S_A + c0] =
                        __floats2half2_rn(fmaxf(acc[mb][nb][0] + bb0, 0.f),
                                          fmaxf(acc[mb][nb][1] + bb1, 0.f));
                    *(__half2*)&A16[(r0 + 8) * S_A + c0] =
                        __floats2half2_rn(fmaxf(acc[mb][nb][2] + bb0, 0.f),
                                          fmaxf(acc[mb][nb][3] + bb1, 0.f));
                }
            }
            #pragma unroll
            for (int mb = 0; mb < 4; ++mb)
                #pragma unroll
                for (int nb = 0; nb < 4; ++nb)
                    #pragma unroll
                    for (int r = 0; r < 4; ++r) acc[mb][nb][r] = 0.f;
        }
    }

    // ---- epilogue: u = D2 + b2; LayerNorm; residual; store ----
    #pragma unroll
    for (int mb = 0; mb < 4; ++mb)
        #pragma unroll
        for (int nb = 0; nb < 4; ++nb) {
            const int c0 = ncol + nb * 8 + 2 * t;
            acc[mb][nb][0] += cb2[c0];
            acc[mb][nb][1] += cb2[c0 + 1];
            acc[mb][nb][2] += cb2[c0];
            acc[mb][nb][3] += cb2[c0 + 1];
        }

    __syncthreads();   // idxs alias dead; part safe to write

    #pragma unroll
    for (int mb = 0; mb < 4; ++mb) {
        float s0 = 0.f, ss0 = 0.f, s1 = 0.f, ss1 = 0.f;
        #pragma unroll
        for (int nb = 0; nb < 4; ++nb) {
            float u0 = acc[mb][nb][0], u1 = acc[mb][nb][1];
            float u2 = acc[mb][nb][2], u3 = acc[mb][nb][3];
            s0 += u0 + u1;  ss0 += u0 * u0 + u1 * u1;
            s1 += u2 + u3;  ss1 += u2 * u2 + u3 * u3;
        }
        #pragma unroll
        for (int m = 1; m < 4; m <<= 1) {
            s0  += __shfl_xor_sync(0xffffffffu, s0,  m);
            ss0 += __shfl_xor_sync(0xffffffffu, ss0, m);
            s1  += __shfl_xor_sync(0xffffffffu, s1,  m);
            ss1 += __shfl_xor_sync(0xffffffffu, ss1, m);
        }
        if (t == 0) {
            int e0 = mrow + mb * 16 + g;
            part[e0 * 4 + wN]       = make_float2(s0, ss0);
            part[(e0 + 8) * 4 + wN] = make_float2(s1, ss1);
        }
    }
    __syncthreads();

    if (tid < TILE) {
        float s = 0.f, ss = 0.f;
        #pragma unroll
        for (int q = 0; q < 4; ++q) {
            float2 p = part[tid * 4 + q];
            s += p.x; ss += p.y;
        }
        float mu  = s * (1.f / 128.f);
        float var = ss * (1.f / 128.f) - mu * mu;
        stats[tid] = make_float2(mu, rsqrtf(var + LN_EPS));
    }
    __syncthreads();

    #pragma unroll
    for (int mb = 0; mb < 4; ++mb) {
        const int r0 = mrow + mb * 16 + g;
        const float2 st0 = stats[r0];
        const float2 st1 = stats[r0 + 8];
        const int eg0 = e_base + r0;
        const int eg1 = eg0 + 8;
        #pragma unroll
        for (int nb = 0; nb < 4; ++nb) {
            const int c0 = ncol + nb * 8 + 2 * t;
            const float gm0 = cgm[c0], gm1 = cgm[c0 + 1];
            const float bt0 = cbt[c0], bt1 = cbt[c0 + 1];
            if (eg0 < n_edges) {
                float2 ef = *(const float2*)(edge_features + (long long)eg0 * HD + c0);
                float2 o;
                o.x = ef.x + (acc[mb][nb][0] - st0.x) * st0.y * gm0 + bt0;
                o.y = ef.y + (acc[mb][nb][1] - st0.x) * st0.y * gm1 + bt1;
                *(float2*)&out[(long long)eg0 * HD + c0] = o;
            }
            if (eg1 < n_edges) {
                float2 ef = *(const float2*)(edge_features + (long long)eg1 * HD + c0);
                float2 o;
                o.x = ef.x + (acc[mb][nb][2] - st1.x) * st1.y * gm0 + bt0;
                o.y = ef.y + (acc[mb][nb][3] - st1.x) * st1.y * gm1 + bt1;
                *(float2*)&out[(long long)eg1 * HD + c0] = o;
            }
        }
    }
}

extern "C" void kernel_launch(void* const* d_in, const int* in_sizes, int n_in,
                              void* d_out, int out_size)
{
    const float* node_inv      = (const float*)d_in[0];
    const float* edge_features = (const float*)d_in[1];
    const void*  edge_src      = d_in[2];
    const void*  edge_dst      = d_in[3];
    const float* W1            = (const float*)d_in[4];
    const float* b1            = (const float*)d_in[5];
    const float* W2            = (const float*)d_in[6];
    const float* b2            = (const float*)d_in[7];
    const float* gamma         = (const float*)d_in[8];
    const float* beta          = (const float*)d_in[9];
    float* out = (float*)d_out;

    int n_edges = in_sizes[1] / HD;
    int n_node_elems = in_sizes[0];
    if (n_node_elems > 50000 * 64) n_node_elems = 50000 * 64;

    prep_node<<<(n_node_elems + 255) / 256, 256>>>(node_inv, n_node_elems);
    prep_w<<<(49152 + 255) / 256, 256>>>(W1, W2);

    cudaFuncSetAttribute(edge_update_mma,
                         cudaFuncAttributeMaxDynamicSharedMemorySize, SMEM_BYTES);

    int grid = (n_edges + TILE - 1) / TILE;
    edge_update_mma<<<grid, THREADS, SMEM_BYTES>>>(
        edge_features, edge_src, edge_dst,
        b1, b2, gamma, beta, out, n_edges);
}